// round 15
// baseline (speedup 1.0000x reference)
#include <cuda_runtime.h>
#include <cuda_bf16.h>
#include <cstdint>
#include <cstddef>

// ---------------- problem constants ----------------
#define BATCH 4
#define CHF   1024            // flat channels = C*4
#define NSP   4096            // H*W = 64*64
#define SCALE_ATTN 0.17677669529663687f

// ---------------- scratch ----------------
// packed bf16 k-pair weight planes: [K/2][M] uint32 words (low16 = even k)
__device__ __align__(16) uint32_t g_wqkv_h [512u*3072u];
__device__ __align__(16) uint32_t g_wqkv_l [512u*3072u];
__device__ __align__(16) uint32_t g_wproj_h[512u*1024u];
__device__ __align__(16) uint32_t g_wproj_l[512u*1024u];
__device__ __align__(16) uint32_t g_wf1_h  [512u*2048u];
__device__ __align__(16) uint32_t g_wf1_l  [512u*2048u];
__device__ __align__(16) uint32_t g_wf2_h  [1024u*1024u];
__device__ __align__(16) uint32_t g_wf2_l  [1024u*1024u];
// packed bf16 activation planes: [b][K/2][NSP]
__device__ __align__(16) uint32_t g_xh  [(size_t)BATCH*512*NSP];
__device__ __align__(16) uint32_t g_xl  [(size_t)BATCH*512*NSP];
__device__ __align__(16) uint32_t g_o2h [(size_t)BATCH*512*NSP];
__device__ __align__(16) uint32_t g_o2l [(size_t)BATCH*512*NSP];
__device__ __align__(16) uint32_t g_x1h [(size_t)BATCH*512*NSP];
__device__ __align__(16) uint32_t g_x1l [(size_t)BATCH*512*NSP];
__device__ __align__(16) uint32_t g_fbh [(size_t)BATCH*1024*NSP];
__device__ __align__(16) uint32_t g_fbl [(size_t)BATCH*1024*NSP];

__device__ __align__(16) float g_wpe   [1024u*16u*9u];
__device__ __align__(16) float g_qkv   [(size_t)BATCH*3072*NSP];
__device__ __align__(16) float g_attno [(size_t)BATCH*CHF*NSP];
__device__ __align__(16) float g_tmp   [(size_t)BATCH*2048*NSP];
__device__ __align__(16) float g_x1    [(size_t)BATCH*CHF*NSP];
__device__ __align__(16) float g_spart [128*4*32*32];   // attention partial S
__device__ __align__(16) float g_pstat [3*2*2048];      // per-stage psum/psqr

__constant__ int   c_comp[16] = {0,1,2,3, 1,0,3,2, 2,3,0,1, 3,2,1,0};
__constant__ float c_sign[16] = {1.f,-1.f,-1.f,-1.f,
                                 1.f, 1.f, 1.f,-1.f,
                                 1.f,-1.f, 1.f, 1.f,
                                 1.f, 1.f,-1.f, 1.f};

// ---------------- helpers ----------------
__device__ __forceinline__ uint32_t smem_u32(const void* p) {
    uint32_t a;
    asm("{ .reg .u64 t; cvta.to.shared.u64 t, %1; cvt.u32.u64 %0, t; }" : "=r"(a) : "l"(p));
    return a;
}
__device__ __forceinline__ void mma16(float c[4], const uint32_t a[4], const uint32_t b[2]) {
    asm volatile("mma.sync.aligned.m16n8k16.row.col.f32.bf16.bf16.f32 "
        "{%0,%1,%2,%3}, {%4,%5,%6,%7}, {%8,%9}, {%0,%1,%2,%3};"
        : "+f"(c[0]), "+f"(c[1]), "+f"(c[2]), "+f"(c[3])
        : "r"(a[0]), "r"(a[1]), "r"(a[2]), "r"(a[3]), "r"(b[0]), "r"(b[1]));
}
// pack two fp32 into bf16x2 (v0 in low 16), plus residual pack
__device__ __forceinline__ void split2(float v0, float v1, uint32_t& wh, uint32_t& wl) {
    __nv_bfloat162 h = __floats2bfloat162_rn(v0, v1);
    wh = *(uint32_t*)&h;
    float r0 = v0 - __uint_as_float(wh << 16);
    float r1 = v1 - __uint_as_float(wh & 0xFFFF0000u);
    __nv_bfloat162 l = __floats2bfloat162_rn(r0, r1);
    wl = *(uint32_t*)&l;
}
__device__ __forceinline__ void cp16(uint32_t sa, const void* ga) {
    asm volatile("cp.async.cg.shared.global [%0], [%1], 16;" :: "r"(sa), "l"(ga));
}
#define CP_COMMIT() asm volatile("cp.async.commit_group;" ::: "memory")
#define CP_WAIT1()  asm volatile("cp.async.wait_group 1;" ::: "memory")

// inline BN coeff from fused partials
__device__ __forceinline__ void bn_coeff(const float* psum, const float* psqr,
                                         const float* gamma, const float* beta,
                                         int ch, float& s, float& h) {
    const float ic = 1.f / 16384.f;
    float mean = psum[ch] * ic;
    float var = psqr[ch] * ic - mean * mean;
    s = gamma[ch] * rsqrtf(var + 1e-5f);
    h = beta[ch] - mean * s;
}

// ---------------- weight expansion -> [K/2][M] planes ----------------
__global__ void expand_w_pk(const float* __restrict__ w, uint32_t* __restrict__ hi,
                            uint32_t* __restrict__ lo, int O, int Ci) {
    int M = 4 * O, KP2 = 2 * Ci;
    int idx = blockIdx.x * 256 + threadIdx.x;
    if (idx >= KP2 * M) return;
    int kp = idx / M, m = idx % M;
    int o = m >> 2, qo = m & 3;
    float v[2];
    #pragma unroll
    for (int j = 0; j < 2; j++) {
        int k = 2 * kp + j;
        int cc = k >> 2, qi = k & 3;
        int tt = qo * 4 + qi;
        v[j] = c_sign[tt] * w[(size_t)c_comp[tt] * O * Ci + (size_t)o * Ci + cc];
    }
    uint32_t wh, wl;
    split2(v[0], v[1], wh, wl);
    hi[idx] = wh; lo[idx] = wl;
}

__global__ void expand_pe_kernel(const float* __restrict__ w, float* __restrict__ out) {
    int idx = blockIdx.x * 256 + threadIdx.x;
    if (idx >= 1024 * 16 * 9) return;
    int kidx = idx % 9; int r = idx / 9;
    int cif = r % 16;   int ocf = r / 16;
    int o = ocf >> 2, qo = ocf & 3, ci = cif >> 2, qi = cif & 3;
    int t = qo * 4 + qi;
    out[idx] = c_sign[t] * w[(size_t)c_comp[t] * (256*4*9) + o * (4*9) + ci * 9 + kidx];
}

// ---------------- split fp32 rows -> packed bf16 planes ----------------
__global__ void split_pack(const float* __restrict__ src, uint32_t* __restrict__ hi,
                           uint32_t* __restrict__ lo, long totalPairs) {
    size_t i4 = (size_t)blockIdx.x * 256 + threadIdx.x;
    size_t tot = (size_t)totalPairs * (NSP / 4);
    if (i4 >= tot) return;
    size_t f = i4 / (NSP / 4);
    int n = (int)(i4 % (NSP / 4)) * 4;
    float4 v0 = *(const float4*)(src + (2 * f) * NSP + n);
    float4 v1 = *(const float4*)(src + (2 * f + 1) * NSP + n);
    uint32_t wh[4], wl[4];
    split2(v0.x, v1.x, wh[0], wl[0]);
    split2(v0.y, v1.y, wh[1], wl[1]);
    split2(v0.z, v1.z, wh[2], wl[2]);
    split2(v0.w, v1.w, wh[3], wl[3]);
    *(uint4*)(hi + f * NSP + n) = make_uint4(wh[0], wh[1], wh[2], wh[3]);
    *(uint4*)(lo + f * NSP + n) = make_uint4(wl[0], wl[1], wl[2], wl[3]);
}

// ---------------- bf16x3 mma GEMM, 3-stage cp.async, 64x64 warp tiles (R10) ----------------
#define KPC    16
#define PSTR   136
#define PLANEW (KPC * PSTR)          // 2176 words
#define STAGEW (4 * PLANEW)          // 8704 words
#define GEMM_SMEM_BYTES (3 * STAGEW * 4)   // 104448 B

template<bool STATS>
__global__ __launch_bounds__(128, 2)
void mma_gemm2(const uint32_t* __restrict__ Ah_g, const uint32_t* __restrict__ Al_g,
               const uint32_t* __restrict__ Bh_g, const uint32_t* __restrict__ Bl_g,
               float* __restrict__ Y, float* psum, float* psqr, int M, int K) {
    extern __shared__ uint32_t sm[];
    uint32_t smb = smem_u32(sm);
    int t = threadIdx.x;
    int wid = t >> 5, lane = t & 31;
    int gid = lane >> 2, tig = lane & 3;
    int wm = (wid >> 1) * 64, wn = (wid & 1) * 64;
    int m0 = blockIdx.y * 128, n0 = blockIdx.x * 128, b = blockIdx.z;
    int KP = K >> 1;
    float* Yb = Y + (size_t)b * M * NSP;

    const uint32_t* base0 = Ah_g + m0;
    const uint32_t* base1 = Al_g + m0;
    const uint32_t* base2 = Bh_g + (size_t)b * KP * NSP + n0;
    const uint32_t* base3 = Bl_g + (size_t)b * KP * NSP + n0;

    int lr = t >> 5;          // 0..3 -> row part
    int lc = lane * 4;        // word col 0..124

    float c[4][8][4];
    #pragma unroll
    for (int mi = 0; mi < 4; mi++)
        #pragma unroll
        for (int nj = 0; nj < 8; nj++)
            #pragma unroll
            for (int q = 0; q < 4; q++) c[mi][nj][q] = 0.f;

    auto ld_chunk = [&](int kc, int stage) {
        uint32_t sbase = smb + 4u * (stage * STAGEW);
        #pragma unroll
        for (int i = 0; i < 16; i++) {
            const int p = i >> 2;
            int r = (i & 3) * 4 + lr;
            const uint32_t* g;
            if (p == 0)      g = base0 + (size_t)(kc * KPC + r) * M + lc;
            else if (p == 1) g = base1 + (size_t)(kc * KPC + r) * M + lc;
            else if (p == 2) g = base2 + (size_t)(kc * KPC + r) * NSP + lc;
            else             g = base3 + (size_t)(kc * KPC + r) * NSP + lc;
            cp16(sbase + 4u * (p * PLANEW + r * PSTR + lc), g);
        }
        CP_COMMIT();
    };

    int T = K / 32;
    ld_chunk(0, 0);
    ld_chunk(1, 1);

    int stage = 0;
    for (int kc = 0; kc < T; kc++) {
        CP_WAIT1();
        __syncthreads();
        if (kc + 2 < T) ld_chunk(kc + 2, (kc + 2) % 3);
        else CP_COMMIT();

        const uint32_t* S  = sm + stage * STAGEW;
        const uint32_t* Ah = S;
        const uint32_t* Al = S + PLANEW;
        const uint32_t* Bh = S + 2 * PLANEW;
        const uint32_t* Bl = S + 3 * PLANEW;

        #pragma unroll
        for (int st = 0; st < 2; st++) {
            int r0 = (st * 8 + tig) * PSTR, r1 = r0 + 4 * PSTR;
            uint32_t ah[4][4], bh[8][2];
            #pragma unroll
            for (int mi = 0; mi < 4; mi++) {
                int mo = wm + 16 * mi + gid;
                ah[mi][0] = Ah[r0 + mo]; ah[mi][1] = Ah[r0 + mo + 8];
                ah[mi][2] = Ah[r1 + mo]; ah[mi][3] = Ah[r1 + mo + 8];
            }
            #pragma unroll
            for (int nj = 0; nj < 8; nj++) {
                int no = wn + 8 * nj + gid;
                bh[nj][0] = Bh[r0 + no]; bh[nj][1] = Bh[r1 + no];
            }
            #pragma unroll
            for (int mi = 0; mi < 4; mi++)
                #pragma unroll
                for (int nj = 0; nj < 8; nj++) mma16(c[mi][nj], ah[mi], bh[nj]);
            {
                uint32_t bl[8][2];
                #pragma unroll
                for (int nj = 0; nj < 8; nj++) {
                    int no = wn + 8 * nj + gid;
                    bl[nj][0] = Bl[r0 + no]; bl[nj][1] = Bl[r1 + no];
                }
                #pragma unroll
                for (int mi = 0; mi < 4; mi++)
                    #pragma unroll
                    for (int nj = 0; nj < 8; nj++) mma16(c[mi][nj], ah[mi], bl[nj]);
            }
            {
                uint32_t al[4][4];
                #pragma unroll
                for (int mi = 0; mi < 4; mi++) {
                    int mo = wm + 16 * mi + gid;
                    al[mi][0] = Al[r0 + mo]; al[mi][1] = Al[r0 + mo + 8];
                    al[mi][2] = Al[r1 + mo]; al[mi][3] = Al[r1 + mo + 8];
                }
                #pragma unroll
                for (int mi = 0; mi < 4; mi++)
                    #pragma unroll
                    for (int nj = 0; nj < 8; nj++) mma16(c[mi][nj], al[mi], bh[nj]);
            }
        }
        stage = (stage + 1 == 3) ? 0 : stage + 1;
    }

    // epilogue: frag rows gid/gid+8, cols 2tig/2tig+1
    #pragma unroll
    for (int mi = 0; mi < 4; mi++) {
        int m = m0 + wm + 16 * mi + gid;
        float* y0 = Yb + (size_t)m * NSP + n0 + wn + 2 * tig;
        float* y1 = y0 + (size_t)8 * NSP;
        #pragma unroll
        for (int nj = 0; nj < 8; nj++) {
            *(float2*)(y0 + nj * 8) = make_float2(c[mi][nj][0], c[mi][nj][1]);
            *(float2*)(y1 + nj * 8) = make_float2(c[mi][nj][2], c[mi][nj][3]);
        }
    }

    if (STATS) {
        __syncthreads();
        float* ssum = (float*)sm;
        float* ssq  = (float*)sm + 128;
        if (t < 128) { ssum[t] = 0.f; ssq[t] = 0.f; }
        __syncthreads();
        #pragma unroll
        for (int mi = 0; mi < 4; mi++) {
            float s0 = 0.f, q0 = 0.f, s1 = 0.f, q1 = 0.f;
            #pragma unroll
            for (int nj = 0; nj < 8; nj++) {
                s0 += c[mi][nj][0] + c[mi][nj][1];
                q0 += c[mi][nj][0] * c[mi][nj][0] + c[mi][nj][1] * c[mi][nj][1];
                s1 += c[mi][nj][2] + c[mi][nj][3];
                q1 += c[mi][nj][2] * c[mi][nj][2] + c[mi][nj][3] * c[mi][nj][3];
            }
            #pragma unroll
            for (int off = 1; off <= 2; off <<= 1) {
                s0 += __shfl_xor_sync(0xffffffffu, s0, off);
                q0 += __shfl_xor_sync(0xffffffffu, q0, off);
                s1 += __shfl_xor_sync(0xffffffffu, s1, off);
                q1 += __shfl_xor_sync(0xffffffffu, q1, off);
            }
            if (tig == 0) {
                int r = wm + 16 * mi + gid;
                atomicAdd(&ssum[r], s0);     atomicAdd(&ssq[r], q0);
                atomicAdd(&ssum[r + 8], s1); atomicAdd(&ssq[r + 8], q1);
            }
        }
        __syncthreads();
        if (t < 128) {
            atomicAdd(&psum[m0 + t], ssum[t]);
            atomicAdd(&psqr[m0 + t], ssq[t]);
        }
    }
}

// ---------------- NT=64 variant: CTA tile 128x64, warp tile 64x32 (R5-proven frag layout) ----------------
#define BSTR64   72                      // 72 mod 32 == 8 -> conflict-free frag reads
#define BPLANE64 (KPC * BSTR64)          // 1152 words
#define STAGE64  (2 * PLANEW + 2 * BPLANE64)   // 6656 words
#define GEMM64_SMEM_BYTES (3 * STAGE64 * 4)    // 79872 B

template<bool STATS>
__global__ __launch_bounds__(128, 2)
void mma_gemm64(const uint32_t* __restrict__ Ah_g, const uint32_t* __restrict__ Al_g,
                const uint32_t* __restrict__ Bh_g, const uint32_t* __restrict__ Bl_g,
                float* __restrict__ Y, float* psum, float* psqr, int M, int K) {
    extern __shared__ uint32_t sm[];
    uint32_t smb = smem_u32(sm);
    int t = threadIdx.x;
    int wid = t >> 5, lane = t & 31;
    int gid = lane >> 2, tig = lane & 3;
    int wm = (wid >> 1) * 64, wn = (wid & 1) * 32;
    int m0 = blockIdx.y * 128, n0 = blockIdx.x * 64, b = blockIdx.z;
    int KP = K >> 1;
    float* Yb = Y + (size_t)b * M * NSP;

    const uint32_t* base0 = Ah_g + m0;
    const uint32_t* base1 = Al_g + m0;
    const uint32_t* base2 = Bh_g + (size_t)b * KP * NSP + n0;
    const uint32_t* base3 = Bl_g + (size_t)b * KP * NSP + n0;

    int lr = t >> 5;              // A staging: 0..3 row part
    int lc = lane * 4;            // A word col 0..124
    int br = t >> 4;              // B staging: 0..7 row part
    int bc = (t & 15) * 4;        // B word col 0..60

    float c[4][4][4];
    #pragma unroll
    for (int mi = 0; mi < 4; mi++)
        #pragma unroll
        for (int nj = 0; nj < 4; nj++)
            #pragma unroll
            for (int q = 0; q < 4; q++) c[mi][nj][q] = 0.f;

    auto ld_chunk = [&](int kc, int stage) {
        uint32_t sbase = smb + 4u * (stage * STAGE64);
        #pragma unroll
        for (int i = 0; i < 8; i++) {                 // A planes
            const int p = i >> 2;
            int r = (i & 3) * 4 + lr;
            const uint32_t* g = (p == 0 ? base0 : base1) + (size_t)(kc * KPC + r) * M + lc;
            cp16(sbase + 4u * (p * PLANEW + r * PSTR + lc), g);
        }
        #pragma unroll
        for (int j = 0; j < 2; j++) {                 // B planes
            int r = br + 8 * j;
            size_t go = (size_t)(kc * KPC + r) * NSP + bc;
            cp16(sbase + 4u * (2 * PLANEW + r * BSTR64 + bc), base2 + go);
            cp16(sbase + 4u * (2 * PLANEW + BPLANE64 + r * BSTR64 + bc), base3 + go);
        }
        CP_COMMIT();
    };

    int T = K / 32;
    ld_chunk(0, 0);
    ld_chunk(1, 1);

    int stage = 0;
    for (int kc = 0; kc < T; kc++) {
        CP_WAIT1();
        __syncthreads();
        if (kc + 2 < T) ld_chunk(kc + 2, (kc + 2) % 3);
        else CP_COMMIT();

        const uint32_t* S  = sm + stage * STAGE64;
        const uint32_t* Ah = S;
        const uint32_t* Al = S + PLANEW;
        const uint32_t* Bh = S + 2 * PLANEW;
        const uint32_t* Bl = S + 2 * PLANEW + BPLANE64;

        #pragma unroll
        for (int st = 0; st < 2; st++) {
            int r0a = (st * 8 + tig) * PSTR,   r1a = r0a + 4 * PSTR;
            int r0b = (st * 8 + tig) * BSTR64, r1b = r0b + 4 * BSTR64;
            uint32_t ah[4][4], bh[4][2];
            #pragma unroll
            for (int mi = 0; mi < 4; mi++) {
                int mo = wm + 16 * mi + gid;
                ah[mi][0] = Ah[r0a + mo]; ah[mi][1] = Ah[r0a + mo + 8];
                ah[mi][2] = Ah[r1a + mo]; ah[mi][3] = Ah[r1a + mo + 8];
            }
            #pragma unroll
            for (int nj = 0; nj < 4; nj++) {
                int no = wn + 8 * nj + gid;
                bh[nj][0] = Bh[r0b + no]; bh[nj][1] = Bh[r1b + no];
            }
            #pragma unroll
            for (int mi = 0; mi < 4; mi++)
                #pragma unroll
                for (int nj = 0; nj < 4; nj++) mma16(c[mi][nj], ah[mi], bh[nj]);
            {
                uint32_t bl[4][2];
                #pragma unroll
                for (int nj = 0; nj < 4; nj++) {
                    int no = wn + 8 * nj + gid;
                    bl[nj][0] = Bl[r0b + no]; bl[nj][1] = Bl[r1b + no];
                }
                #pragma unroll
                for (int mi = 0; mi < 4; mi++)
                    #pragma unroll
                    for (int nj = 0; nj < 4; nj++) mma16(c[mi][nj], ah[mi], bl[nj]);
            }
            {
                uint32_t al[4][4];
                #pragma unroll
                for (int mi = 0; mi < 4; mi++) {
                    int mo = wm + 16 * mi + gid;
                    al[mi][0] = Al[r0a + mo]; al[mi][1] = Al[r0a + mo + 8];
                    al[mi][2] = Al[r1a + mo]; al[mi][3] = Al[r1a + mo + 8];
                }
                #pragma unroll
                for (int mi = 0; mi < 4; mi++)
                    #pragma unroll
                    for (int nj = 0; nj < 4; nj++) mma16(c[mi][nj], al[mi], bh[nj]);
            }
        }
        stage = (stage + 1 == 3) ? 0 : stage + 1;
    }

    // epilogue
    #pragma unroll
    for (int mi = 0; mi < 4; mi++) {
        int m = m0 + wm + 16 * mi + gid;
        float* y0 = Yb + (size_t)m * NSP + n0 + wn + 2 * tig;
        float* y1 = y0 + (size_t)8 * NSP;
        #pragma unroll
        for (int nj = 0; nj < 4; nj++) {
            *(float2*)(y0 + nj * 8) = make_float2(c[mi][nj][0], c[mi][nj][1]);
            *(float2*)(y1 + nj * 8) = make_float2(c[mi][nj][2], c[mi][nj][3]);
        }
    }

    if (STATS) {
        __syncthreads();
        float* ssum = (float*)sm;
        float* ssq  = (float*)sm + 128;
        if (t < 128) { ssum[t] = 0.f; ssq[t] = 0.f; }
        __syncthreads();
        #pragma unroll
        for (int mi = 0; mi < 4; mi++) {
            float s0 = 0.f, q0 = 0.f, s1 = 0.f, q1 = 0.f;
            #pragma unroll
            for (int nj = 0; nj < 4; nj++) {
                s0 += c[mi][nj][0] + c[mi][nj][1];
                q0 += c[mi][nj][0] * c[mi][nj][0] + c[mi][nj][1] * c[mi][nj][1];
                s1 += c[mi][nj][2] + c[mi][nj][3];
                q1 += c[mi][nj][2] * c[mi][nj][2] + c[mi][nj][3] * c[mi][nj][3];
            }
            #pragma unroll
            for (int off = 1; off <= 2; off <<= 1) {
                s0 += __shfl_xor_sync(0xffffffffu, s0, off);
                q0 += __shfl_xor_sync(0xffffffffu, q0, off);
                s1 += __shfl_xor_sync(0xffffffffu, s1, off);
                q1 += __shfl_xor_sync(0xffffffffu, q1, off);
            }
            if (tig == 0) {
                int r = wm + 16 * mi + gid;
                atomicAdd(&ssum[r], s0);     atomicAdd(&ssq[r], q0);
                atomicAdd(&ssum[r + 8], s1); atomicAdd(&ssq[r + 8], q1);
            }
        }
        __syncthreads();
        if (t < 128) {
            atomicAdd(&psum[m0 + t], ssum[t]);
            atomicAdd(&psqr[m0 + t], ssq[t]);
        }
    }
}

// ---------------- attention ----------------
__global__ __launch_bounds__(256)
void attn_qk(const float* __restrict__ qkv, float* __restrict__ spart) {
    int bid = blockIdx.x, quarter = blockIdx.y;
    int b = bid >> 5, h = (bid >> 2) & 7, q = bid & 3;
    const float* base = qkv + (size_t)b * 3072 * NSP;
    const float* Qp = base + ((size_t)(h * 96 + 0)  * 4 + q) * NSP;
    const float* Kp = base + ((size_t)(h * 96 + 32) * 4 + q) * NSP;
    const size_t RS = (size_t)4 * NSP;

    __shared__ float Qs[32][132];
    __shared__ float Ks[32][132];
    __shared__ float sred[4][32][32];

    int t = threadIdx.x;
    int kg = t >> 6, lt = t & 63;
    int c0 = lt >> 3, d0 = lt & 7, kb = kg * 32;

    float s[4][4];
    #pragma unroll
    for (int i = 0; i < 4; i++)
        #pragma unroll
        for (int j = 0; j < 4; j++) s[i][j] = 0.f;

    int nbeg = quarter * 1024;
    for (int n0 = nbeg; n0 < nbeg + 1024; n0 += 128) {
        #pragma unroll
        for (int i = 0; i < 4; i++) {
            int fl = t + i * 256;
            int r = fl >> 5, cc = fl & 31;
            *(float4*)&Qs[r][cc * 4] = *(const float4*)&Qp[(size_t)r * RS + n0 + cc * 4];
            *(float4*)&Ks[r][cc * 4] = *(const float4*)&Kp[(size_t)r * RS + n0 + cc * 4];
        }
        __syncthreads();
        for (int kk = 0; kk < 32; kk++) {
            float qv[4], kv[4];
            #pragma unroll
            for (int i = 0; i < 4; i++) qv[i] = Qs[c0 + 8 * i][kb + kk];
            #pragma unroll
            for (int j = 0; j < 4; j++) kv[j] = Ks[d0 + 8 * j][kb + kk];
            #pragma unroll
            for (int i = 0; i < 4; i++)
                #pragma unroll
                for (int j = 0; j < 4; j++) s[i][j] += qv[i] * kv[j];
        }
        __syncthreads();
    }
    #pragma unroll
    for (int i = 0; i < 4; i++)
        #pragma unroll
        for (int j = 0; j < 4; j++)
            sred[kg][c0 + 8 * i][d0 + 8 * j] = s[i][j];
    __syncthreads();

    float* sp = spart + ((size_t)bid * 4 + quarter) * 1024;
    for (int e = t; e < 1024; e += 256) {
        int cc = e >> 5, dd = e & 31;
        sp[e] = sred[0][cc][dd] + sred[1][cc][dd] + sred[2][cc][dd] + sred[3][cc][dd];
    }
}

// attn_av with inline softmax + register blocking
__global__ __launch_bounds__(256)
void attn_av(const float* __restrict__ qkv, const float* __restrict__ spart,
             float* __restrict__ o) {
    int bid = blockIdx.x, quarter = blockIdx.y;
    int b = bid >> 5, h = (bid >> 2) & 7, q = bid & 3;
    const float* Vp = qkv + (size_t)b * 3072 * NSP + ((size_t)(h * 96 + 64) * 4 + q) * NSP;
    const size_t RS = (size_t)4 * NSP;

    __shared__ float Sm[32][32];
    int t = threadIdx.x;
    if (t < 32) {
        int c = t;
        const float* sp = spart + (size_t)bid * 4096;
        float rowv[32];
        float mx = -1e30f;
        #pragma unroll
        for (int d = 0; d < 32; d++) {
            float v = (sp[c * 32 + d] + sp[1024 + c * 32 + d] +
                       sp[2048 + c * 32 + d] + sp[3072 + c * 32 + d]) * SCALE_ATTN;
            rowv[d] = v; mx = fmaxf(mx, v);
        }
        float sum = 0.f;
        #pragma unroll
        for (int d = 0; d < 32; d++) { float e = expf(rowv[d] - mx); rowv[d] = e; sum += e; }
        float inv = 1.f / sum;
        #pragma unroll
        for (int d = 0; d < 32; d++) Sm[c][d] = rowv[d] * inv;
    }
    __syncthreads();

    float* ob = o + (size_t)b * CHF * NSP;
    int n = quarter * 1024 + t * 4;

    #pragma unroll
    for (int half = 0; half < 2; half++) {
        float acc[16][4];
        #pragma unroll
        for (int c = 0; c < 16; c++)
            #pragma unroll
            for (int i = 0; i < 4; i++) acc[c][i] = 0.f;
        #pragma unroll 4
        for (int d = 0; d < 32; d++) {
            float4 v4 = *(const float4*)(Vp + (size_t)d * RS + n);
            #pragma unroll
            for (int c = 0; c < 16; c++) {
                float s = Sm[half * 16 + c][d];
                acc[c][0] += s * v4.x; acc[c][1] += s * v4.y;
                acc[c][2] += s * v4.z; acc[c][3] += s * v4.w;
            }
        }
        #pragma unroll
        for (int c = 0; c < 16; c++) {
            int cc = half * 16 + c;
            *(float4*)(ob + ((size_t)((h * 32 + cc) * 4 + q)) * NSP + n) =
                make_float4(acc[c][0], acc[c][1], acc[c][2], acc[c][3]);
        }
    }
}

// ---------------- grouped 3x3 quaternion conv + residual -> bf16 planes directly ----------------
__global__ __launch_bounds__(256)
void peconv_kernel(const float* __restrict__ in, const float* __restrict__ wpe,
                   uint32_t* __restrict__ hi, uint32_t* __restrict__ lo) {
    extern __shared__ float smem[];
    float* ins = smem;
    float* wts = smem + 19008;

    int ytile = blockIdx.x, g = blockIdx.y, b = blockIdx.z;
    int t = threadIdx.x;
    int lane = t & 31, w = t >> 5;

    const float* inb = in + ((size_t)b * CHF + g * 16) * NSP;
    for (int idx = t; idx < 16 * 18 * 66; idx += 256) {
        int xx = idx % 66; int r = idx / 66;
        int yy = r % 18;   int ci = r / 18;
        int gy = ytile * 16 + yy - 1;
        int gx = xx - 1;
        float v = 0.f;
        if (gy >= 0 && gy < 64 && gx >= 0 && gx < 64)
            v = inb[(size_t)ci * NSP + gy * 64 + gx];
        ins[idx] = v;
    }
    for (int idx = t; idx < 16 * 16 * 9; idx += 256) {
        int kidx = idx % 9; int r = idx / 9;
        int ci = r % 16;    int oc = r / 16;
        wts[idx] = wpe[((size_t)(g * 16 + oc)) * (16 * 9) + ci * 9 + kidx];
    }
    __syncthreads();

    int oc = t >> 4, ly = t & 15;
    int gy = ytile * 16 + ly;
    const float* wrow = wts + oc * (16 * 9);
    size_t fbase = ((size_t)b * 512 + g * 8 + w) * NSP + (size_t)gy * 64;

    for (int x0 = 0; x0 < 64; x0 += 16) {
        float acc[16];
        #pragma unroll
        for (int xi = 0; xi < 16; xi++)
            acc[xi] = ins[(oc * 18 + ly + 1) * 66 + x0 + xi + 1];   // residual
        for (int ci = 0; ci < 16; ci++) {
            #pragma unroll
            for (int kh = 0; kh < 3; kh++) {
                const float* ir = &ins[(ci * 18 + ly + kh) * 66 + x0];
                float w0 = wrow[ci * 9 + kh * 3 + 0];
                float w1 = wrow[ci * 9 + kh * 3 + 1];
                float w2 = wrow[ci * 9 + kh * 3 + 2];
                #pragma unroll
                for (int xi = 0; xi < 16; xi++)
                    acc[xi] += w0 * ir[xi] + w1 * ir[xi + 1] + w2 * ir[xi + 2];
            }
        }
        #pragma unroll
        for (int xi = 0; xi < 16; xi++) {
            float other = __shfl_xor_sync(0xffffffffu, acc[xi], 16);
            if (lane < 16) {
                uint32_t wh, wl;
                split2(acc[xi], other, wh, wl);
                hi[fbase + x0 + xi] = wh;
                lo[fbase + x0 + xi] = wl;
            }
        }
    }
}
#define PE_SMEM ((19008 + 2304) * 4)

// ---------------- fused BN(inline coeff) + residual, emitting fp32 + split planes ----------------
__global__ void ew_res_split(const float* __restrict__ X, const float* __restrict__ Yg,
                             const float* __restrict__ psum, const float* __restrict__ psqr,
                             const float* __restrict__ gamma, const float* __restrict__ beta,
                             float* __restrict__ x1, uint32_t* __restrict__ hi,
                             uint32_t* __restrict__ lo, int Mch) {
    size_t i4 = (size_t)blockIdx.x * 256 + threadIdx.x;
    size_t tot = (size_t)BATCH * (Mch / 2) * (NSP / 4);
    if (i4 >= tot) return;
    size_t f = i4 / (NSP / 4);
    int n = (int)(i4 % (NSP / 4)) * 4;
    int ch0 = (int)((2 * f) % Mch);
    float s0, h0, s1, h1;
    bn_coeff(psum, psqr, gamma, beta, ch0, s0, h0);
    bn_coeff(psum, psqr, gamma, beta, ch0 + 1, s1, h1);
    float4 y0 = *(const float4*)(Yg + (2 * f) * NSP + n);
    float4 y1 = *(const float4*)(Yg + (2 * f + 1) * NSP + n);
    float4 xv0 = *(const float4*)(X + (2 * f) * NSP + n);
    float4 xv1 = *(const float4*)(X + (2 * f + 1) * NSP + n);
    float4 r0, r1;
    r0.x = xv0.x + y0.x * s0 + h0; r0.y = xv0.y + y0.y * s0 + h0;
    r0.z = xv0.z + y0.z * s0 + h0; r0.w = xv0.w + y0.w * s0 + h0;
    r1.x = xv1.x + y1.x * s1 + h1; r1.y = xv1.y + y1.y * s1 + h1;
    r1.z = xv1.z + y1.z * s1 + h1; r1.w = xv1.w + y1.w * s1 + h1;
    *(float4*)(x1 + (2 * f) * NSP + n) = r0;
    *(float4*)(x1 + (2 * f + 1) * NSP + n) = r1;
    uint32_t wh[4], wl[4];
    split2(r0.x, r1.x, wh[0], wl[0]);
    split2(r0.y, r1.y, wh[1], wl[1]);
    split2(r0.z, r1.z, wh[2], wl[2]);
    split2(r0.w, r1.w, wh[3], wl[3]);
    *(uint4*)(hi + f * NSP + n) = make_uint4(wh[0], wh[1], wh[2], wh[3]);
    *(uint4*)(lo + f * NSP + n) = make_uint4(wl[0], wl[1], wl[2], wl[3]);
}

// ---------------- fused BN(inline) + relu, emitting split planes only ----------------
__global__ void ew_relu_split(const float* __restrict__ Yg,
                              const float* __restrict__ psum, const float* __restrict__ psqr,
                              const float* __restrict__ gamma, const float* __restrict__ beta,
                              uint32_t* __restrict__ hi, uint32_t* __restrict__ lo, int Mch) {
    size_t i4 = (size_t)blockIdx.x * 256 + threadIdx.x;
    size_t tot = (size_t)BATCH * (Mch / 2) * (NSP / 4);
    if (i4 >= tot) return;
    size_t f = i4 / (NSP / 4);
    int n = (int)(i4 % (NSP / 4)) * 4;
    int ch0 = (int)((2 * f) % Mch);
    float s0, h0, s1, h1;
    bn_coeff(psum, psqr, gamma, beta, ch0, s0, h0);
    bn_coeff(psum, psqr, gamma, beta, ch0 + 1, s1, h1);
    float4 y0 = *(const float4*)(Yg + (2 * f) * NSP + n);
    float4 y1 = *(const float4*)(Yg + (2 * f + 1) * NSP + n);
    float4 r0, r1;
    r0.x = fmaxf(y0.x * s0 + h0, 0.f); r0.y = fmaxf(y0.y * s0 + h0, 0.f);
    r0.z = fmaxf(y0.z * s0 + h0, 0.f); r0.w = fmaxf(y0.w * s0 + h0, 0.f);
    r1.x = fmaxf(y1.x * s1 + h1, 0.f); r1.y = fmaxf(y1.y * s1 + h1, 0.f);
    r1.z = fmaxf(y1.z * s1 + h1, 0.f); r1.w = fmaxf(y1.w * s1 + h1, 0.f);
    uint32_t wh[4], wl[4];
    split2(r0.x, r1.x, wh[0], wl[0]);
    split2(r0.y, r1.y, wh[1], wl[1]);
    split2(r0.z, r1.z, wh[2], wl[2]);
    split2(r0.w, r1.w, wh[3], wl[3]);
    *(uint4*)(hi + f * NSP + n) = make_uint4(wh[0], wh[1], wh[2], wh[3]);
    *(uint4*)(lo + f * NSP + n) = make_uint4(wl[0], wl[1], wl[2], wl[3]);
}

// ---------------- plain BN(inline) + residual (final output) ----------------
__global__ void ew_bn_res_kernel(const float* __restrict__ X, const float* __restrict__ Yg,
                                 const float* __restrict__ psum, const float* __restrict__ psqr,
                                 const float* __restrict__ gamma, const float* __restrict__ beta,
                                 float* __restrict__ out, int Mch) {
    size_t i4 = (size_t)blockIdx.x * 256 + threadIdx.x;
    size_t total4 = (size_t)4 * Mch * NSP / 4;
    if (i4 >= total4) return;
    size_t i = i4 * 4;
    int ch = (int)((i / NSP) % Mch);
    float s, h;
    bn_coeff(psum, psqr, gamma, beta, ch, s, h);
    float4 y = *(const float4*)(Yg + i);
    float4 x = *(const float4*)(X + i);
    float4 r;
    r.x = x.x + y.x * s + h; r.y = x.y + y.y * s + h;
    r.z = x.z + y.z * s + h; r.w = x.w + y.w * s + h;
    *(float4*)(out + i) = r;
}

// ---------------- host launcher ----------------
extern "C" void kernel_launch(void* const* d_in, const int* in_sizes, int n_in,
                              void* d_out, int out_size) {
    const float* x      = (const float*)d_in[0];
    const float* w_qkv  = (const float*)d_in[1];
    const float* w_proj = (const float*)d_in[2];
    const float* w_pe   = (const float*)d_in[3];
    const float* gn     = (const float*)d_in[4];
    const float* bn     = (const float*)d_in[5];
    const float* w_f1   = (const float*)d_in[6];
    const float* gf1    = (const float*)d_in[7];
    const float* bf1    = (const float*)d_in[8];
    const float* w_f2   = (const float*)d_in[9];
    const float* gf2    = (const float*)d_in[10];
    const float* bf2    = (const float*)d_in[11];
    float* out = (float*)d_out;

    void *p;
    uint32_t *qh, *ql, *ph, *pl, *f1h, *f1l, *f2h, *f2l;
    uint32_t *xh, *xl, *o2h, *o2l, *x1h, *x1l, *fbh, *fbl;
    float *wpe, *qkv, *attno, *tmp, *x1, *spart, *pstat;
    cudaGetSymbolAddress(&p, g_wqkv_h);  qh  = (uint32_t*)p;
    cudaGetSymbolAddress(&p, g_wqkv_l);  ql  = (uint32_t*)p;
    cudaGetSymbolAddress(&p, g_wproj_h); ph  = (uint32_t*)p;
    cudaGetSymbolAddress(&p, g_wproj_l); pl  = (uint32_t*)p;
    cudaGetSymbolAddress(&p, g_wf1_h);   f1h = (uint32_t*)p;
    cudaGetSymbolAddress(&p, g_wf1_l);   f1l = (uint32_t*)p;
    cudaGetSymbolAddress(&p, g_wf2_h);   f2h = (uint32_t*)p;
    cudaGetSymbolAddress(&p, g_wf2_l);   f2l = (uint32_t*)p;
    cudaGetSymbolAddress(&p, g_xh);      xh  = (uint32_t*)p;
    cudaGetSymbolAddress(&p, g_xl);      xl  = (uint32_t*)p;
    cudaGetSymbolAddress(&p, g_o2h);     o2h = (uint32_t*)p;
    cudaGetSymbolAddress(&p, g_o2l);     o2l = (uint32_t*)p;
    cudaGetSymbolAddress(&p, g_x1h);     x1h = (uint32_t*)p;
    cudaGetSymbolAddress(&p, g_x1l);     x1l = (uint32_t*)p;
    cudaGetSymbolAddress(&p, g_fbh);     fbh = (uint32_t*)p;
    cudaGetSymbolAddress(&p, g_fbl);     fbl = (uint32_t*)p;
    cudaGetSymbolAddress(&p, g_wpe);     wpe = (float*)p;
    cudaGetSymbolAddress(&p, g_qkv);     qkv = (float*)p;
    cudaGetSymbolAddress(&p, g_attno);   attno = (float*)p;
    cudaGetSymbolAddress(&p, g_tmp);     tmp = (float*)p;
    cudaGetSymbolAddress(&p, g_x1);      x1  = (float*)p;
    cudaGetSymbolAddress(&p, g_spart);   spart = (float*)p;
    cudaGetSymbolAddress(&p, g_pstat);   pstat = (float*)p;

    float* ps0 = pstat;           float* pq0 = pstat + 2048;
    float* ps1 = pstat + 4096;    float* pq1 = pstat + 6144;
    float* ps2 = pstat + 8192;    float* pq2 = pstat + 10240;

    cudaFuncSetAttribute(mma_gemm2<false>, cudaFuncAttributeMaxDynamicSharedMemorySize, GEMM_SMEM_BYTES);
    cudaFuncSetAttribute(mma_gemm2<true>,  cudaFuncAttributeMaxDynamicSharedMemorySize, GEMM_SMEM_BYTES);
    cudaFuncSetAttribute(mma_gemm64<true>, cudaFuncAttributeMaxDynamicSharedMemorySize, GEMM64_SMEM_BYTES);
    cudaFuncSetAttribute(peconv_kernel, cudaFuncAttributeMaxDynamicSharedMemorySize, PE_SMEM);

    // 0. zero stat accumulators
    cudaMemsetAsync(pstat, 0, 3 * 2 * 2048 * sizeof(float));

    // 1. weight expansions -> packed bf16 hi/lo planes
    expand_w_pk<<<(512 * 3072 + 255) / 256, 256>>>(w_qkv,  qh,  ql,  768, 256);
    expand_w_pk<<<(512 * 1024 + 255) / 256, 256>>>(w_proj, ph,  pl,  256, 256);
    expand_w_pk<<<(512 * 2048 + 255) / 256, 256>>>(w_f1,   f1h, f1l, 512, 256);
    expand_w_pk<<<(1024 * 1024 + 255) / 256, 256>>>(w_f2,  f2h, f2l, 256, 512);
    expand_pe_kernel<<<(1024 * 16 * 9 + 255) / 256, 256>>>(w_pe, wpe);

    // 2. split x -> planes, qkv GEMM (NT=128 kernel, 10.4 waves)
    split_pack<<<(int)((size_t)BATCH * 512 * (NSP / 4) / 256), 256>>>(x, xh, xl, BATCH * 512);
    mma_gemm2<false><<<dim3(32, 24, BATCH), 128, GEMM_SMEM_BYTES>>>(
        qh, ql, xh, xl, qkv, nullptr, nullptr, 3072, 1024);

    // 3. channel attention
    attn_qk<<<dim3(128, 4), 256>>>(qkv, spart);
    attn_av<<<dim3(128, 4), 256>>>(qkv, spart, attno);

    // 4. positional conv + residual -> o2 planes directly
    peconv_kernel<<<dim3(4, 64, BATCH), 256, PE_SMEM>>>(attno, wpe, o2h, o2l);

    // 5. proj GEMM (+stats, NT=64 anti-tail) + BN residual -> x1 (+ planes)
    mma_gemm64<true><<<dim3(64, 8, BATCH), 128, GEMM64_SMEM_BYTES>>>(
        ph, pl, o2h, o2l, tmp, ps0, pq0, 1024, 1024);
    ew_res_split<<<(int)((size_t)BATCH * 512 * (NSP / 4) / 256), 256>>>(
        x, tmp, ps0, pq0, gn, bn, x1, x1h, x1l, 1024);

    // 6. f1 GEMM (+stats, NT=128, 6.9 waves) + BN relu -> fb planes
    mma_gemm2<true><<<dim3(32, 16, BATCH), 128, GEMM_SMEM_BYTES>>>(
        f1h, f1l, x1h, x1l, tmp, ps1, pq1, 2048, 1024);
    ew_relu_split<<<(int)((size_t)BATCH * 1024 * (NSP / 4) / 256), 256>>>(
        tmp, ps1, pq1, gf1, bf1, fbh, fbl, 2048);

    // 7. f2 GEMM (+stats, NT=64 anti-tail) + BN residual -> out
    mma_gemm64<true><<<dim3(64, 8, BATCH), 128, GEMM64_SMEM_BYTES>>>(
        f2h, f2l, fbh, fbl, tmp, ps2, pq2, 1024, 2048);
    ew_bn_res_kernel<<<(int)((size_t)4 * 1024 * NSP / 4 / 256), 256>>>(
        x1, tmp, ps2, pq2, gf2, bf2, out, 1024);

    (void)in_sizes; (void)n_in; (void)out_size;
}

// round 16
// speedup vs baseline: 1.0612x; 1.0612x over previous
#include <cuda_runtime.h>
#include <cuda_bf16.h>
#include <cstdint>
#include <cstddef>

// ---------------- problem constants ----------------
#define BATCH 4
#define CHF   1024            // flat channels = C*4
#define NSP   4096            // H*W = 64*64
#define SCALE_ATTN 0.17677669529663687f

// ---------------- scratch ----------------
// packed bf16 k-pair weight planes: [K/2][M] uint32 words (low16 = even k)
__device__ __align__(16) uint32_t g_wqkv_h [512u*3072u];
__device__ __align__(16) uint32_t g_wqkv_l [512u*3072u];
__device__ __align__(16) uint32_t g_wproj_h[512u*1024u];
__device__ __align__(16) uint32_t g_wproj_l[512u*1024u];
__device__ __align__(16) uint32_t g_wf1_h  [512u*2048u];
__device__ __align__(16) uint32_t g_wf1_l  [512u*2048u];
__device__ __align__(16) uint32_t g_wf2_h  [1024u*1024u];
__device__ __align__(16) uint32_t g_wf2_l  [1024u*1024u];
// packed bf16 activation planes: [b][K/2][NSP]
__device__ __align__(16) uint32_t g_xh  [(size_t)BATCH*512*NSP];
__device__ __align__(16) uint32_t g_xl  [(size_t)BATCH*512*NSP];
__device__ __align__(16) uint32_t g_o2h [(size_t)BATCH*512*NSP];
__device__ __align__(16) uint32_t g_o2l [(size_t)BATCH*512*NSP];
__device__ __align__(16) uint32_t g_x1h [(size_t)BATCH*512*NSP];
__device__ __align__(16) uint32_t g_x1l [(size_t)BATCH*512*NSP];
__device__ __align__(16) uint32_t g_fbh [(size_t)BATCH*1024*NSP];
__device__ __align__(16) uint32_t g_fbl [(size_t)BATCH*1024*NSP];

__device__ __align__(16) float g_wpe   [1024u*16u*9u];
__device__ __align__(16) float g_qkv   [(size_t)BATCH*3072*NSP];
__device__ __align__(16) float g_attno [(size_t)BATCH*CHF*NSP];
__device__ __align__(16) float g_tmp   [(size_t)BATCH*2048*NSP];
__device__ __align__(16) float g_x1    [(size_t)BATCH*CHF*NSP];
__device__ __align__(16) float g_spart [128*4*32*32];   // attention partial S
__device__ __align__(16) float g_pstat [3*2*2048];      // per-stage psum/psqr

__constant__ int   c_comp[16] = {0,1,2,3, 1,0,3,2, 2,3,0,1, 3,2,1,0};
__constant__ float c_sign[16] = {1.f,-1.f,-1.f,-1.f,
                                 1.f, 1.f, 1.f,-1.f,
                                 1.f,-1.f, 1.f, 1.f,
                                 1.f, 1.f,-1.f, 1.f};

// ---------------- helpers ----------------
__device__ __forceinline__ uint32_t smem_u32(const void* p) {
    uint32_t a;
    asm("{ .reg .u64 t; cvta.to.shared.u64 t, %1; cvt.u32.u64 %0, t; }" : "=r"(a) : "l"(p));
    return a;
}
__device__ __forceinline__ void mma16(float c[4], const uint32_t a[4], const uint32_t b[2]) {
    asm volatile("mma.sync.aligned.m16n8k16.row.col.f32.bf16.bf16.f32 "
        "{%0,%1,%2,%3}, {%4,%5,%6,%7}, {%8,%9}, {%0,%1,%2,%3};"
        : "+f"(c[0]), "+f"(c[1]), "+f"(c[2]), "+f"(c[3])
        : "r"(a[0]), "r"(a[1]), "r"(a[2]), "r"(a[3]), "r"(b[0]), "r"(b[1]));
}
// pack two fp32 into bf16x2 (v0 in low 16), plus residual pack
__device__ __forceinline__ void split2(float v0, float v1, uint32_t& wh, uint32_t& wl) {
    __nv_bfloat162 h = __floats2bfloat162_rn(v0, v1);
    wh = *(uint32_t*)&h;
    float r0 = v0 - __uint_as_float(wh << 16);
    float r1 = v1 - __uint_as_float(wh & 0xFFFF0000u);
    __nv_bfloat162 l = __floats2bfloat162_rn(r0, r1);
    wl = *(uint32_t*)&l;
}
__device__ __forceinline__ void cp16(uint32_t sa, const void* ga) {
    asm volatile("cp.async.cg.shared.global [%0], [%1], 16;" :: "r"(sa), "l"(ga));
}
#define CP_COMMIT() asm volatile("cp.async.commit_group;" ::: "memory")
#define CP_WAIT1()  asm volatile("cp.async.wait_group 1;" ::: "memory")

// inline BN coeff from fused partials
__device__ __forceinline__ void bn_coeff(const float* psum, const float* psqr,
                                         const float* gamma, const float* beta,
                                         int ch, float& s, float& h) {
    const float ic = 1.f / 16384.f;
    float mean = psum[ch] * ic;
    float var = psqr[ch] * ic - mean * mean;
    s = gamma[ch] * rsqrtf(var + 1e-5f);
    h = beta[ch] - mean * s;
}

// ---------------- weight expansion -> [K/2][M] planes ----------------
__global__ void expand_w_pk(const float* __restrict__ w, uint32_t* __restrict__ hi,
                            uint32_t* __restrict__ lo, int O, int Ci) {
    int M = 4 * O, KP2 = 2 * Ci;
    int idx = blockIdx.x * 256 + threadIdx.x;
    if (idx >= KP2 * M) return;
    int kp = idx / M, m = idx % M;
    int o = m >> 2, qo = m & 3;
    float v[2];
    #pragma unroll
    for (int j = 0; j < 2; j++) {
        int k = 2 * kp + j;
        int cc = k >> 2, qi = k & 3;
        int tt = qo * 4 + qi;
        v[j] = c_sign[tt] * w[(size_t)c_comp[tt] * O * Ci + (size_t)o * Ci + cc];
    }
    uint32_t wh, wl;
    split2(v[0], v[1], wh, wl);
    hi[idx] = wh; lo[idx] = wl;
}

__global__ void expand_pe_kernel(const float* __restrict__ w, float* __restrict__ out) {
    int idx = blockIdx.x * 256 + threadIdx.x;
    if (idx >= 1024 * 16 * 9) return;
    int kidx = idx % 9; int r = idx / 9;
    int cif = r % 16;   int ocf = r / 16;
    int o = ocf >> 2, qo = ocf & 3, ci = cif >> 2, qi = cif & 3;
    int t = qo * 4 + qi;
    out[idx] = c_sign[t] * w[(size_t)c_comp[t] * (256*4*9) + o * (4*9) + ci * 9 + kidx];
}

// ---------------- split fp32 rows -> packed bf16 planes ----------------
__global__ void split_pack(const float* __restrict__ src, uint32_t* __restrict__ hi,
                           uint32_t* __restrict__ lo, long totalPairs) {
    size_t i4 = (size_t)blockIdx.x * 256 + threadIdx.x;
    size_t tot = (size_t)totalPairs * (NSP / 4);
    if (i4 >= tot) return;
    size_t f = i4 / (NSP / 4);
    int n = (int)(i4 % (NSP / 4)) * 4;
    float4 v0 = *(const float4*)(src + (2 * f) * NSP + n);
    float4 v1 = *(const float4*)(src + (2 * f + 1) * NSP + n);
    uint32_t wh[4], wl[4];
    split2(v0.x, v1.x, wh[0], wl[0]);
    split2(v0.y, v1.y, wh[1], wl[1]);
    split2(v0.z, v1.z, wh[2], wl[2]);
    split2(v0.w, v1.w, wh[3], wl[3]);
    *(uint4*)(hi + f * NSP + n) = make_uint4(wh[0], wh[1], wh[2], wh[3]);
    *(uint4*)(lo + f * NSP + n) = make_uint4(wl[0], wl[1], wl[2], wl[3]);
}

// ---------------- bf16x3 mma GEMM, 3-stage cp.async, 64x64 warp tiles (R10 final) ----------------
#define KPC    16
#define PSTR   136
#define PLANEW (KPC * PSTR)          // 2176 words
#define STAGEW (4 * PLANEW)          // 8704 words
#define GEMM_SMEM_BYTES (3 * STAGEW * 4)   // 104448 B

template<bool STATS>
__global__ __launch_bounds__(128, 2)
void mma_gemm2(const uint32_t* __restrict__ Ah_g, const uint32_t* __restrict__ Al_g,
               const uint32_t* __restrict__ Bh_g, const uint32_t* __restrict__ Bl_g,
               float* __restrict__ Y, float* psum, float* psqr, int M, int K) {
    extern __shared__ uint32_t sm[];
    uint32_t smb = smem_u32(sm);
    int t = threadIdx.x;
    int wid = t >> 5, lane = t & 31;
    int gid = lane >> 2, tig = lane & 3;
    int wm = (wid >> 1) * 64, wn = (wid & 1) * 64;
    int m0 = blockIdx.y * 128, n0 = blockIdx.x * 128, b = blockIdx.z;
    int KP = K >> 1;
    float* Yb = Y + (size_t)b * M * NSP;

    const uint32_t* base0 = Ah_g + m0;
    const uint32_t* base1 = Al_g + m0;
    const uint32_t* base2 = Bh_g + (size_t)b * KP * NSP + n0;
    const uint32_t* base3 = Bl_g + (size_t)b * KP * NSP + n0;

    int lr = t >> 5;          // 0..3 -> row part
    int lc = lane * 4;        // word col 0..124

    float c[4][8][4];
    #pragma unroll
    for (int mi = 0; mi < 4; mi++)
        #pragma unroll
        for (int nj = 0; nj < 8; nj++)
            #pragma unroll
            for (int q = 0; q < 4; q++) c[mi][nj][q] = 0.f;

    auto ld_chunk = [&](int kc, int stage) {
        uint32_t sbase = smb + 4u * (stage * STAGEW);
        #pragma unroll
        for (int i = 0; i < 16; i++) {
            const int p = i >> 2;
            int r = (i & 3) * 4 + lr;
            const uint32_t* g;
            if (p == 0)      g = base0 + (size_t)(kc * KPC + r) * M + lc;
            else if (p == 1) g = base1 + (size_t)(kc * KPC + r) * M + lc;
            else if (p == 2) g = base2 + (size_t)(kc * KPC + r) * NSP + lc;
            else             g = base3 + (size_t)(kc * KPC + r) * NSP + lc;
            cp16(sbase + 4u * (p * PLANEW + r * PSTR + lc), g);
        }
        CP_COMMIT();
    };

    int T = K / 32;
    ld_chunk(0, 0);
    ld_chunk(1, 1);

    int stage = 0;
    for (int kc = 0; kc < T; kc++) {
        CP_WAIT1();
        __syncthreads();
        if (kc + 2 < T) ld_chunk(kc + 2, (kc + 2) % 3);
        else CP_COMMIT();

        const uint32_t* S  = sm + stage * STAGEW;
        const uint32_t* Ah = S;
        const uint32_t* Al = S + PLANEW;
        const uint32_t* Bh = S + 2 * PLANEW;
        const uint32_t* Bl = S + 3 * PLANEW;

        #pragma unroll
        for (int st = 0; st < 2; st++) {
            int r0 = (st * 8 + tig) * PSTR, r1 = r0 + 4 * PSTR;
            uint32_t ah[4][4], bh[8][2];
            #pragma unroll
            for (int mi = 0; mi < 4; mi++) {
                int mo = wm + 16 * mi + gid;
                ah[mi][0] = Ah[r0 + mo]; ah[mi][1] = Ah[r0 + mo + 8];
                ah[mi][2] = Ah[r1 + mo]; ah[mi][3] = Ah[r1 + mo + 8];
            }
            #pragma unroll
            for (int nj = 0; nj < 8; nj++) {
                int no = wn + 8 * nj + gid;
                bh[nj][0] = Bh[r0 + no]; bh[nj][1] = Bh[r1 + no];
            }
            #pragma unroll
            for (int mi = 0; mi < 4; mi++)
                #pragma unroll
                for (int nj = 0; nj < 8; nj++) mma16(c[mi][nj], ah[mi], bh[nj]);
            {
                uint32_t bl[8][2];
                #pragma unroll
                for (int nj = 0; nj < 8; nj++) {
                    int no = wn + 8 * nj + gid;
                    bl[nj][0] = Bl[r0 + no]; bl[nj][1] = Bl[r1 + no];
                }
                #pragma unroll
                for (int mi = 0; mi < 4; mi++)
                    #pragma unroll
                    for (int nj = 0; nj < 8; nj++) mma16(c[mi][nj], ah[mi], bl[nj]);
            }
            {
                uint32_t al[4][4];
                #pragma unroll
                for (int mi = 0; mi < 4; mi++) {
                    int mo = wm + 16 * mi + gid;
                    al[mi][0] = Al[r0 + mo]; al[mi][1] = Al[r0 + mo + 8];
                    al[mi][2] = Al[r1 + mo]; al[mi][3] = Al[r1 + mo + 8];
                }
                #pragma unroll
                for (int mi = 0; mi < 4; mi++)
                    #pragma unroll
                    for (int nj = 0; nj < 8; nj++) mma16(c[mi][nj], al[mi], bh[nj]);
            }
        }
        stage = (stage + 1 == 3) ? 0 : stage + 1;
    }

    // epilogue: frag rows gid/gid+8, cols 2tig/2tig+1
    #pragma unroll
    for (int mi = 0; mi < 4; mi++) {
        int m = m0 + wm + 16 * mi + gid;
        float* y0 = Yb + (size_t)m * NSP + n0 + wn + 2 * tig;
        float* y1 = y0 + (size_t)8 * NSP;
        #pragma unroll
        for (int nj = 0; nj < 8; nj++) {
            *(float2*)(y0 + nj * 8) = make_float2(c[mi][nj][0], c[mi][nj][1]);
            *(float2*)(y1 + nj * 8) = make_float2(c[mi][nj][2], c[mi][nj][3]);
        }
    }

    if (STATS) {
        __syncthreads();                 // pipeline smem no longer read; reuse
        float* ssum = (float*)sm;        // [128]
        float* ssq  = (float*)sm + 128;  // [128]
        if (t < 128) { ssum[t] = 0.f; ssq[t] = 0.f; }
        __syncthreads();
        #pragma unroll
        for (int mi = 0; mi < 4; mi++) {
            float s0 = 0.f, q0 = 0.f, s1 = 0.f, q1 = 0.f;
            #pragma unroll
            for (int nj = 0; nj < 8; nj++) {
                s0 += c[mi][nj][0] + c[mi][nj][1];
                q0 += c[mi][nj][0] * c[mi][nj][0] + c[mi][nj][1] * c[mi][nj][1];
                s1 += c[mi][nj][2] + c[mi][nj][3];
                q1 += c[mi][nj][2] * c[mi][nj][2] + c[mi][nj][3] * c[mi][nj][3];
            }
            #pragma unroll
            for (int off = 1; off <= 2; off <<= 1) {
                s0 += __shfl_xor_sync(0xffffffffu, s0, off);
                q0 += __shfl_xor_sync(0xffffffffu, q0, off);
                s1 += __shfl_xor_sync(0xffffffffu, s1, off);
                q1 += __shfl_xor_sync(0xffffffffu, q1, off);
            }
            if (tig == 0) {
                int r = wm + 16 * mi + gid;
                atomicAdd(&ssum[r], s0);     atomicAdd(&ssq[r], q0);
                atomicAdd(&ssum[r + 8], s1); atomicAdd(&ssq[r + 8], q1);
            }
        }
        __syncthreads();
        if (t < 128) {
            atomicAdd(&psum[m0 + t], ssum[t]);
            atomicAdd(&psqr[m0 + t], ssq[t]);
        }
    }
}

// ---------------- attention ----------------
__global__ __launch_bounds__(256)
void attn_qk(const float* __restrict__ qkv, float* __restrict__ spart) {
    int bid = blockIdx.x, quarter = blockIdx.y;
    int b = bid >> 5, h = (bid >> 2) & 7, q = bid & 3;
    const float* base = qkv + (size_t)b * 3072 * NSP;
    const float* Qp = base + ((size_t)(h * 96 + 0)  * 4 + q) * NSP;
    const float* Kp = base + ((size_t)(h * 96 + 32) * 4 + q) * NSP;
    const size_t RS = (size_t)4 * NSP;

    __shared__ float Qs[32][132];
    __shared__ float Ks[32][132];
    __shared__ float sred[4][32][32];

    int t = threadIdx.x;
    int kg = t >> 6, lt = t & 63;
    int c0 = lt >> 3, d0 = lt & 7, kb = kg * 32;

    float s[4][4];
    #pragma unroll
    for (int i = 0; i < 4; i++)
        #pragma unroll
        for (int j = 0; j < 4; j++) s[i][j] = 0.f;

    int nbeg = quarter * 1024;
    for (int n0 = nbeg; n0 < nbeg + 1024; n0 += 128) {
        #pragma unroll
        for (int i = 0; i < 4; i++) {
            int fl = t + i * 256;
            int r = fl >> 5, cc = fl & 31;
            *(float4*)&Qs[r][cc * 4] = *(const float4*)&Qp[(size_t)r * RS + n0 + cc * 4];
            *(float4*)&Ks[r][cc * 4] = *(const float4*)&Kp[(size_t)r * RS + n0 + cc * 4];
        }
        __syncthreads();
        for (int kk = 0; kk < 32; kk++) {
            float qv[4], kv[4];
            #pragma unroll
            for (int i = 0; i < 4; i++) qv[i] = Qs[c0 + 8 * i][kb + kk];
            #pragma unroll
            for (int j = 0; j < 4; j++) kv[j] = Ks[d0 + 8 * j][kb + kk];
            #pragma unroll
            for (int i = 0; i < 4; i++)
                #pragma unroll
                for (int j = 0; j < 4; j++) s[i][j] += qv[i] * kv[j];
        }
        __syncthreads();
    }
    #pragma unroll
    for (int i = 0; i < 4; i++)
        #pragma unroll
        for (int j = 0; j < 4; j++)
            sred[kg][c0 + 8 * i][d0 + 8 * j] = s[i][j];
    __syncthreads();

    float* sp = spart + ((size_t)bid * 4 + quarter) * 1024;
    for (int e = t; e < 1024; e += 256) {
        int cc = e >> 5, dd = e & 31;
        sp[e] = sred[0][cc][dd] + sred[1][cc][dd] + sred[2][cc][dd] + sred[3][cc][dd];
    }
}

// attn_av with inline softmax + register blocking
__global__ __launch_bounds__(256)
void attn_av(const float* __restrict__ qkv, const float* __restrict__ spart,
             float* __restrict__ o) {
    int bid = blockIdx.x, quarter = blockIdx.y;
    int b = bid >> 5, h = (bid >> 2) & 7, q = bid & 3;
    const float* Vp = qkv + (size_t)b * 3072 * NSP + ((size_t)(h * 96 + 64) * 4 + q) * NSP;
    const size_t RS = (size_t)4 * NSP;

    __shared__ float Sm[32][32];
    int t = threadIdx.x;
    if (t < 32) {
        int c = t;
        const float* sp = spart + (size_t)bid * 4096;
        float rowv[32];
        float mx = -1e30f;
        #pragma unroll
        for (int d = 0; d < 32; d++) {
            float v = (sp[c * 32 + d] + sp[1024 + c * 32 + d] +
                       sp[2048 + c * 32 + d] + sp[3072 + c * 32 + d]) * SCALE_ATTN;
            rowv[d] = v; mx = fmaxf(mx, v);
        }
        float sum = 0.f;
        #pragma unroll
        for (int d = 0; d < 32; d++) { float e = expf(rowv[d] - mx); rowv[d] = e; sum += e; }
        float inv = 1.f / sum;
        #pragma unroll
        for (int d = 0; d < 32; d++) Sm[c][d] = rowv[d] * inv;
    }
    __syncthreads();

    float* ob = o + (size_t)b * CHF * NSP;
    int n = quarter * 1024 + t * 4;

    #pragma unroll
    for (int half = 0; half < 2; half++) {
        float acc[16][4];
        #pragma unroll
        for (int c = 0; c < 16; c++)
            #pragma unroll
            for (int i = 0; i < 4; i++) acc[c][i] = 0.f;
        #pragma unroll 4
        for (int d = 0; d < 32; d++) {
            float4 v4 = *(const float4*)(Vp + (size_t)d * RS + n);
            #pragma unroll
            for (int c = 0; c < 16; c++) {
                float s = Sm[half * 16 + c][d];
                acc[c][0] += s * v4.x; acc[c][1] += s * v4.y;
                acc[c][2] += s * v4.z; acc[c][3] += s * v4.w;
            }
        }
        #pragma unroll
        for (int c = 0; c < 16; c++) {
            int cc = half * 16 + c;
            *(float4*)(ob + ((size_t)((h * 32 + cc) * 4 + q)) * NSP + n) =
                make_float4(acc[c][0], acc[c][1], acc[c][2], acc[c][3]);
        }
    }
}

// ---------------- grouped 3x3 quaternion conv + residual -> bf16 planes directly ----------------
__global__ __launch_bounds__(256)
void peconv_kernel(const float* __restrict__ in, const float* __restrict__ wpe,
                   uint32_t* __restrict__ hi, uint32_t* __restrict__ lo) {
    extern __shared__ float smem[];
    float* ins = smem;
    float* wts = smem + 19008;

    int ytile = blockIdx.x, g = blockIdx.y, b = blockIdx.z;
    int t = threadIdx.x;
    int lane = t & 31, w = t >> 5;

    const float* inb = in + ((size_t)b * CHF + g * 16) * NSP;
    for (int idx = t; idx < 16 * 18 * 66; idx += 256) {
        int xx = idx % 66; int r = idx / 66;
        int yy = r % 18;   int ci = r / 18;
        int gy = ytile * 16 + yy - 1;
        int gx = xx - 1;
        float v = 0.f;
        if (gy >= 0 && gy < 64 && gx >= 0 && gx < 64)
            v = inb[(size_t)ci * NSP + gy * 64 + gx];
        ins[idx] = v;
    }
    for (int idx = t; idx < 16 * 16 * 9; idx += 256) {
        int kidx = idx % 9; int r = idx / 9;
        int ci = r % 16;    int oc = r / 16;
        wts[idx] = wpe[((size_t)(g * 16 + oc)) * (16 * 9) + ci * 9 + kidx];
    }
    __syncthreads();

    int oc = t >> 4, ly = t & 15;
    int gy = ytile * 16 + ly;
    const float* wrow = wts + oc * (16 * 9);
    size_t fbase = ((size_t)b * 512 + g * 8 + w) * NSP + (size_t)gy * 64;

    for (int x0 = 0; x0 < 64; x0 += 16) {
        float acc[16];
        #pragma unroll
        for (int xi = 0; xi < 16; xi++)
            acc[xi] = ins[(oc * 18 + ly + 1) * 66 + x0 + xi + 1];   // residual
        for (int ci = 0; ci < 16; ci++) {
            #pragma unroll
            for (int kh = 0; kh < 3; kh++) {
                const float* ir = &ins[(ci * 18 + ly + kh) * 66 + x0];
                float w0 = wrow[ci * 9 + kh * 3 + 0];
                float w1 = wrow[ci * 9 + kh * 3 + 1];
                float w2 = wrow[ci * 9 + kh * 3 + 2];
                #pragma unroll
                for (int xi = 0; xi < 16; xi++)
                    acc[xi] += w0 * ir[xi] + w1 * ir[xi + 1] + w2 * ir[xi + 2];
            }
        }
        #pragma unroll
        for (int xi = 0; xi < 16; xi++) {
            float other = __shfl_xor_sync(0xffffffffu, acc[xi], 16);
            if (lane < 16) {
                uint32_t wh, wl;
                split2(acc[xi], other, wh, wl);
                hi[fbase + x0 + xi] = wh;
                lo[fbase + x0 + xi] = wl;
            }
        }
    }
}
#define PE_SMEM ((19008 + 2304) * 4)

// ---------------- fused BN(inline coeff) + residual, emitting fp32 + split planes ----------------
__global__ void ew_res_split(const float* __restrict__ X, const float* __restrict__ Yg,
                             const float* __restrict__ psum, const float* __restrict__ psqr,
                             const float* __restrict__ gamma, const float* __restrict__ beta,
                             float* __restrict__ x1, uint32_t* __restrict__ hi,
                             uint32_t* __restrict__ lo, int Mch) {
    size_t i4 = (size_t)blockIdx.x * 256 + threadIdx.x;
    size_t tot = (size_t)BATCH * (Mch / 2) * (NSP / 4);
    if (i4 >= tot) return;
    size_t f = i4 / (NSP / 4);
    int n = (int)(i4 % (NSP / 4)) * 4;
    int ch0 = (int)((2 * f) % Mch);
    float s0, h0, s1, h1;
    bn_coeff(psum, psqr, gamma, beta, ch0, s0, h0);
    bn_coeff(psum, psqr, gamma, beta, ch0 + 1, s1, h1);
    float4 y0 = *(const float4*)(Yg + (2 * f) * NSP + n);
    float4 y1 = *(const float4*)(Yg + (2 * f + 1) * NSP + n);
    float4 xv0 = *(const float4*)(X + (2 * f) * NSP + n);
    float4 xv1 = *(const float4*)(X + (2 * f + 1) * NSP + n);
    float4 r0, r1;
    r0.x = xv0.x + y0.x * s0 + h0; r0.y = xv0.y + y0.y * s0 + h0;
    r0.z = xv0.z + y0.z * s0 + h0; r0.w = xv0.w + y0.w * s0 + h0;
    r1.x = xv1.x + y1.x * s1 + h1; r1.y = xv1.y + y1.y * s1 + h1;
    r1.z = xv1.z + y1.z * s1 + h1; r1.w = xv1.w + y1.w * s1 + h1;
    *(float4*)(x1 + (2 * f) * NSP + n) = r0;
    *(float4*)(x1 + (2 * f + 1) * NSP + n) = r1;
    uint32_t wh[4], wl[4];
    split2(r0.x, r1.x, wh[0], wl[0]);
    split2(r0.y, r1.y, wh[1], wl[1]);
    split2(r0.z, r1.z, wh[2], wl[2]);
    split2(r0.w, r1.w, wh[3], wl[3]);
    *(uint4*)(hi + f * NSP + n) = make_uint4(wh[0], wh[1], wh[2], wh[3]);
    *(uint4*)(lo + f * NSP + n) = make_uint4(wl[0], wl[1], wl[2], wl[3]);
}

// ---------------- fused BN(inline) + relu, emitting split planes only ----------------
__global__ void ew_relu_split(const float* __restrict__ Yg,
                              const float* __restrict__ psum, const float* __restrict__ psqr,
                              const float* __restrict__ gamma, const float* __restrict__ beta,
                              uint32_t* __restrict__ hi, uint32_t* __restrict__ lo, int Mch) {
    size_t i4 = (size_t)blockIdx.x * 256 + threadIdx.x;
    size_t tot = (size_t)BATCH * (Mch / 2) * (NSP / 4);
    if (i4 >= tot) return;
    size_t f = i4 / (NSP / 4);
    int n = (int)(i4 % (NSP / 4)) * 4;
    int ch0 = (int)((2 * f) % Mch);
    float s0, h0, s1, h1;
    bn_coeff(psum, psqr, gamma, beta, ch0, s0, h0);
    bn_coeff(psum, psqr, gamma, beta, ch0 + 1, s1, h1);
    float4 y0 = *(const float4*)(Yg + (2 * f) * NSP + n);
    float4 y1 = *(const float4*)(Yg + (2 * f + 1) * NSP + n);
    float4 r0, r1;
    r0.x = fmaxf(y0.x * s0 + h0, 0.f); r0.y = fmaxf(y0.y * s0 + h0, 0.f);
    r0.z = fmaxf(y0.z * s0 + h0, 0.f); r0.w = fmaxf(y0.w * s0 + h0, 0.f);
    r1.x = fmaxf(y1.x * s1 + h1, 0.f); r1.y = fmaxf(y1.y * s1 + h1, 0.f);
    r1.z = fmaxf(y1.z * s1 + h1, 0.f); r1.w = fmaxf(y1.w * s1 + h1, 0.f);
    uint32_t wh[4], wl[4];
    split2(r0.x, r1.x, wh[0], wl[0]);
    split2(r0.y, r1.y, wh[1], wl[1]);
    split2(r0.z, r1.z, wh[2], wl[2]);
    split2(r0.w, r1.w, wh[3], wl[3]);
    *(uint4*)(hi + f * NSP + n) = make_uint4(wh[0], wh[1], wh[2], wh[3]);
    *(uint4*)(lo + f * NSP + n) = make_uint4(wl[0], wl[1], wl[2], wl[3]);
}

// ---------------- plain BN(inline) + residual (final output) ----------------
__global__ void ew_bn_res_kernel(const float* __restrict__ X, const float* __restrict__ Yg,
                                 const float* __restrict__ psum, const float* __restrict__ psqr,
                                 const float* __restrict__ gamma, const float* __restrict__ beta,
                                 float* __restrict__ out, int Mch) {
    size_t i4 = (size_t)blockIdx.x * 256 + threadIdx.x;
    size_t total4 = (size_t)4 * Mch * NSP / 4;
    if (i4 >= total4) return;
    size_t i = i4 * 4;
    int ch = (int)((i / NSP) % Mch);
    float s, h;
    bn_coeff(psum, psqr, gamma, beta, ch, s, h);
    float4 y = *(const float4*)(Yg + i);
    float4 x = *(const float4*)(X + i);
    float4 r;
    r.x = x.x + y.x * s + h; r.y = x.y + y.y * s + h;
    r.z = x.z + y.z * s + h; r.w = x.w + y.w * s + h;
    *(float4*)(out + i) = r;
}

// ---------------- host launcher ----------------
extern "C" void kernel_launch(void* const* d_in, const int* in_sizes, int n_in,
                              void* d_out, int out_size) {
    const float* x      = (const float*)d_in[0];
    const float* w_qkv  = (const float*)d_in[1];
    const float* w_proj = (const float*)d_in[2];
    const float* w_pe   = (const float*)d_in[3];
    const float* gn     = (const float*)d_in[4];
    const float* bn     = (const float*)d_in[5];
    const float* w_f1   = (const float*)d_in[6];
    const float* gf1    = (const float*)d_in[7];
    const float* bf1    = (const float*)d_in[8];
    const float* w_f2   = (const float*)d_in[9];
    const float* gf2    = (const float*)d_in[10];
    const float* bf2    = (const float*)d_in[11];
    float* out = (float*)d_out;

    void *p;
    uint32_t *qh, *ql, *ph, *pl, *f1h, *f1l, *f2h, *f2l;
    uint32_t *xh, *xl, *o2h, *o2l, *x1h, *x1l, *fbh, *fbl;
    float *wpe, *qkv, *attno, *tmp, *x1, *spart, *pstat;
    cudaGetSymbolAddress(&p, g_wqkv_h);  qh  = (uint32_t*)p;
    cudaGetSymbolAddress(&p, g_wqkv_l);  ql  = (uint32_t*)p;
    cudaGetSymbolAddress(&p, g_wproj_h); ph  = (uint32_t*)p;
    cudaGetSymbolAddress(&p, g_wproj_l); pl  = (uint32_t*)p;
    cudaGetSymbolAddress(&p, g_wf1_h);   f1h = (uint32_t*)p;
    cudaGetSymbolAddress(&p, g_wf1_l);   f1l = (uint32_t*)p;
    cudaGetSymbolAddress(&p, g_wf2_h);   f2h = (uint32_t*)p;
    cudaGetSymbolAddress(&p, g_wf2_l);   f2l = (uint32_t*)p;
    cudaGetSymbolAddress(&p, g_xh);      xh  = (uint32_t*)p;
    cudaGetSymbolAddress(&p, g_xl);      xl  = (uint32_t*)p;
    cudaGetSymbolAddress(&p, g_o2h);     o2h = (uint32_t*)p;
    cudaGetSymbolAddress(&p, g_o2l);     o2l = (uint32_t*)p;
    cudaGetSymbolAddress(&p, g_x1h);     x1h = (uint32_t*)p;
    cudaGetSymbolAddress(&p, g_x1l);     x1l = (uint32_t*)p;
    cudaGetSymbolAddress(&p, g_fbh);     fbh = (uint32_t*)p;
    cudaGetSymbolAddress(&p, g_fbl);     fbl = (uint32_t*)p;
    cudaGetSymbolAddress(&p, g_wpe);     wpe = (float*)p;
    cudaGetSymbolAddress(&p, g_qkv);     qkv = (float*)p;
    cudaGetSymbolAddress(&p, g_attno);   attno = (float*)p;
    cudaGetSymbolAddress(&p, g_tmp);     tmp = (float*)p;
    cudaGetSymbolAddress(&p, g_x1);      x1  = (float*)p;
    cudaGetSymbolAddress(&p, g_spart);   spart = (float*)p;
    cudaGetSymbolAddress(&p, g_pstat);   pstat = (float*)p;

    float* ps0 = pstat;           float* pq0 = pstat + 2048;
    float* ps1 = pstat + 4096;    float* pq1 = pstat + 6144;
    float* ps2 = pstat + 8192;    float* pq2 = pstat + 10240;

    cudaFuncSetAttribute(mma_gemm2<false>, cudaFuncAttributeMaxDynamicSharedMemorySize, GEMM_SMEM_BYTES);
    cudaFuncSetAttribute(mma_gemm2<true>,  cudaFuncAttributeMaxDynamicSharedMemorySize, GEMM_SMEM_BYTES);
    cudaFuncSetAttribute(peconv_kernel, cudaFuncAttributeMaxDynamicSharedMemorySize, PE_SMEM);

    // 0. zero stat accumulators
    cudaMemsetAsync(pstat, 0, 3 * 2 * 2048 * sizeof(float));

    // 1. weight expansions -> packed bf16 hi/lo planes
    expand_w_pk<<<(512 * 3072 + 255) / 256, 256>>>(w_qkv,  qh,  ql,  768, 256);
    expand_w_pk<<<(512 * 1024 + 255) / 256, 256>>>(w_proj, ph,  pl,  256, 256);
    expand_w_pk<<<(512 * 2048 + 255) / 256, 256>>>(w_f1,   f1h, f1l, 512, 256);
    expand_w_pk<<<(1024 * 1024 + 255) / 256, 256>>>(w_f2,  f2h, f2l, 256, 512);
    expand_pe_kernel<<<(1024 * 16 * 9 + 255) / 256, 256>>>(w_pe, wpe);

    // 2. split x -> planes, qkv GEMM (no stats)
    split_pack<<<(int)((size_t)BATCH * 512 * (NSP / 4) / 256), 256>>>(x, xh, xl, BATCH * 512);
    mma_gemm2<false><<<dim3(32, 24, BATCH), 128, GEMM_SMEM_BYTES>>>(
        qh, ql, xh, xl, qkv, nullptr, nullptr, 3072, 1024);

    // 3. channel attention
    attn_qk<<<dim3(128, 4), 256>>>(qkv, spart);
    attn_av<<<dim3(128, 4), 256>>>(qkv, spart, attno);

    // 4. positional conv + residual -> o2 planes directly
    peconv_kernel<<<dim3(4, 64, BATCH), 256, PE_SMEM>>>(attno, wpe, o2h, o2l);

    // 5. proj GEMM (+stats) + BN residual -> x1 (+ planes)
    mma_gemm2<true><<<dim3(32, 8, BATCH), 128, GEMM_SMEM_BYTES>>>(
        ph, pl, o2h, o2l, tmp, ps0, pq0, 1024, 1024);
    ew_res_split<<<(int)((size_t)BATCH * 512 * (NSP / 4) / 256), 256>>>(
        x, tmp, ps0, pq0, gn, bn, x1, x1h, x1l, 1024);

    // 6. f1 GEMM (+stats) + BN relu -> fb planes
    mma_gemm2<true><<<dim3(32, 16, BATCH), 128, GEMM_SMEM_BYTES>>>(
        f1h, f1l, x1h, x1l, tmp, ps1, pq1, 2048, 1024);
    ew_relu_split<<<(int)((size_t)BATCH * 1024 * (NSP / 4) / 256), 256>>>(
        tmp, ps1, pq1, gf1, bf1, fbh, fbl, 2048);

    // 7. f2 GEMM (+stats) + BN residual -> out
    mma_gemm2<true><<<dim3(32, 8, BATCH), 128, GEMM_SMEM_BYTES>>>(
        f2h, f2l, fbh, fbl, tmp, ps2, pq2, 1024, 2048);
    ew_bn_res_kernel<<<(int)((size_t)4 * 1024 * NSP / 4 / 256), 256>>>(
        x1, tmp, ps2, pq2, gf2, bf2, out, 1024);

    (void)in_sizes; (void)n_in; (void)out_size;
}

// round 17
// speedup vs baseline: 1.0650x; 1.0035x over previous
#include <cuda_runtime.h>
#include <cuda_bf16.h>
#include <cstdint>
#include <cstddef>

// ---------------- problem constants ----------------
#define BATCH 4
#define CHF   1024            // flat channels = C*4
#define NSP   4096            // H*W = 64*64
#define SCALE_ATTN 0.17677669529663687f

// ---------------- scratch ----------------
// packed bf16 k-pair weight planes: [K/2][M] uint32 words (low16 = even k)
__device__ __align__(16) uint32_t g_wqkv_h [512u*3072u];
__device__ __align__(16) uint32_t g_wqkv_l [512u*3072u];
__device__ __align__(16) uint32_t g_wproj_h[512u*1024u];
__device__ __align__(16) uint32_t g_wproj_l[512u*1024u];
__device__ __align__(16) uint32_t g_wf1_h  [512u*2048u];
__device__ __align__(16) uint32_t g_wf1_l  [512u*2048u];
__device__ __align__(16) uint32_t g_wf2_h  [1024u*1024u];
__device__ __align__(16) uint32_t g_wf2_l  [1024u*1024u];
// packed bf16 activation planes: [b][K/2][NSP]
__device__ __align__(16) uint32_t g_xh  [(size_t)BATCH*512*NSP];
__device__ __align__(16) uint32_t g_xl  [(size_t)BATCH*512*NSP];
__device__ __align__(16) uint32_t g_o2h [(size_t)BATCH*512*NSP];
__device__ __align__(16) uint32_t g_o2l [(size_t)BATCH*512*NSP];
__device__ __align__(16) uint32_t g_x1h [(size_t)BATCH*512*NSP];
__device__ __align__(16) uint32_t g_x1l [(size_t)BATCH*512*NSP];
__device__ __align__(16) uint32_t g_fbh [(size_t)BATCH*1024*NSP];
__device__ __align__(16) uint32_t g_fbl [(size_t)BATCH*1024*NSP];

__device__ __align__(16) float g_wpe   [1024u*16u*9u];
__device__ __align__(16) float g_qkv   [(size_t)BATCH*3072*NSP];
__device__ __align__(16) float g_attno [(size_t)BATCH*CHF*NSP];
__device__ __align__(16) float g_tmp   [(size_t)BATCH*2048*NSP];
__device__ __align__(16) float g_spart [128*4*32*32];   // attention partial S
__device__ __align__(16) float g_pstat [3*2*2048];      // per-stage psum/psqr

__constant__ int   c_comp[16] = {0,1,2,3, 1,0,3,2, 2,3,0,1, 3,2,1,0};
__constant__ float c_sign[16] = {1.f,-1.f,-1.f,-1.f,
                                 1.f, 1.f, 1.f,-1.f,
                                 1.f,-1.f, 1.f, 1.f,
                                 1.f, 1.f,-1.f, 1.f};

// ---------------- helpers ----------------
__device__ __forceinline__ uint32_t smem_u32(const void* p) {
    uint32_t a;
    asm("{ .reg .u64 t; cvta.to.shared.u64 t, %1; cvt.u32.u64 %0, t; }" : "=r"(a) : "l"(p));
    return a;
}
__device__ __forceinline__ void mma16(float c[4], const uint32_t a[4], const uint32_t b[2]) {
    asm volatile("mma.sync.aligned.m16n8k16.row.col.f32.bf16.bf16.f32 "
        "{%0,%1,%2,%3}, {%4,%5,%6,%7}, {%8,%9}, {%0,%1,%2,%3};"
        : "+f"(c[0]), "+f"(c[1]), "+f"(c[2]), "+f"(c[3])
        : "r"(a[0]), "r"(a[1]), "r"(a[2]), "r"(a[3]), "r"(b[0]), "r"(b[1]));
}
// pack two fp32 into bf16x2 (v0 in low 16), plus residual pack
__device__ __forceinline__ void split2(float v0, float v1, uint32_t& wh, uint32_t& wl) {
    __nv_bfloat162 h = __floats2bfloat162_rn(v0, v1);
    wh = *(uint32_t*)&h;
    float r0 = v0 - __uint_as_float(wh << 16);
    float r1 = v1 - __uint_as_float(wh & 0xFFFF0000u);
    __nv_bfloat162 l = __floats2bfloat162_rn(r0, r1);
    wl = *(uint32_t*)&l;
}
// reconstruct the two packed fp32 values (to ~2^-16 rel) from hi/lo words
__device__ __forceinline__ void recon2(uint32_t wh, uint32_t wl, float& v0, float& v1) {
    v0 = __uint_as_float(wh << 16) + __uint_as_float(wl << 16);
    v1 = __uint_as_float(wh & 0xFFFF0000u) + __uint_as_float(wl & 0xFFFF0000u);
}
__device__ __forceinline__ void cp16(uint32_t sa, const void* ga) {
    asm volatile("cp.async.cg.shared.global [%0], [%1], 16;" :: "r"(sa), "l"(ga));
}
#define CP_COMMIT() asm volatile("cp.async.commit_group;" ::: "memory")
#define CP_WAIT1()  asm volatile("cp.async.wait_group 1;" ::: "memory")

// inline BN coeff from fused partials
__device__ __forceinline__ void bn_coeff(const float* psum, const float* psqr,
                                         const float* gamma, const float* beta,
                                         int ch, float& s, float& h) {
    const float ic = 1.f / 16384.f;
    float mean = psum[ch] * ic;
    float var = psqr[ch] * ic - mean * mean;
    s = gamma[ch] * rsqrtf(var + 1e-5f);
    h = beta[ch] - mean * s;
}

// ---------------- weight expansion -> [K/2][M] planes ----------------
__global__ void expand_w_pk(const float* __restrict__ w, uint32_t* __restrict__ hi,
                            uint32_t* __restrict__ lo, int O, int Ci) {
    int M = 4 * O, KP2 = 2 * Ci;
    int idx = blockIdx.x * 256 + threadIdx.x;
    if (idx >= KP2 * M) return;
    int kp = idx / M, m = idx % M;
    int o = m >> 2, qo = m & 3;
    float v[2];
    #pragma unroll
    for (int j = 0; j < 2; j++) {
        int k = 2 * kp + j;
        int cc = k >> 2, qi = k & 3;
        int tt = qo * 4 + qi;
        v[j] = c_sign[tt] * w[(size_t)c_comp[tt] * O * Ci + (size_t)o * Ci + cc];
    }
    uint32_t wh, wl;
    split2(v[0], v[1], wh, wl);
    hi[idx] = wh; lo[idx] = wl;
}

__global__ void expand_pe_kernel(const float* __restrict__ w, float* __restrict__ out) {
    int idx = blockIdx.x * 256 + threadIdx.x;
    if (idx >= 1024 * 16 * 9) return;
    int kidx = idx % 9; int r = idx / 9;
    int cif = r % 16;   int ocf = r / 16;
    int o = ocf >> 2, qo = ocf & 3, ci = cif >> 2, qi = cif & 3;
    int t = qo * 4 + qi;
    out[idx] = c_sign[t] * w[(size_t)c_comp[t] * (256*4*9) + o * (4*9) + ci * 9 + kidx];
}

// ---------------- split fp32 rows -> packed bf16 planes ----------------
__global__ void split_pack(const float* __restrict__ src, uint32_t* __restrict__ hi,
                           uint32_t* __restrict__ lo, long totalPairs) {
    size_t i4 = (size_t)blockIdx.x * 256 + threadIdx.x;
    size_t tot = (size_t)totalPairs * (NSP / 4);
    if (i4 >= tot) return;
    size_t f = i4 / (NSP / 4);
    int n = (int)(i4 % (NSP / 4)) * 4;
    float4 v0 = *(const float4*)(src + (2 * f) * NSP + n);
    float4 v1 = *(const float4*)(src + (2 * f + 1) * NSP + n);
    uint32_t wh[4], wl[4];
    split2(v0.x, v1.x, wh[0], wl[0]);
    split2(v0.y, v1.y, wh[1], wl[1]);
    split2(v0.z, v1.z, wh[2], wl[2]);
    split2(v0.w, v1.w, wh[3], wl[3]);
    *(uint4*)(hi + f * NSP + n) = make_uint4(wh[0], wh[1], wh[2], wh[3]);
    *(uint4*)(lo + f * NSP + n) = make_uint4(wl[0], wl[1], wl[2], wl[3]);
}

// ---------------- bf16x3 mma GEMM, 3-stage cp.async, 64x64 warp tiles (R10 final) ----------------
#define KPC    16
#define PSTR   136
#define PLANEW (KPC * PSTR)          // 2176 words
#define STAGEW (4 * PLANEW)          // 8704 words
#define GEMM_SMEM_BYTES (3 * STAGEW * 4)   // 104448 B

template<bool STATS>
__global__ __launch_bounds__(128, 2)
void mma_gemm2(const uint32_t* __restrict__ Ah_g, const uint32_t* __restrict__ Al_g,
               const uint32_t* __restrict__ Bh_g, const uint32_t* __restrict__ Bl_g,
               float* __restrict__ Y, float* psum, float* psqr, int M, int K) {
    extern __shared__ uint32_t sm[];
    uint32_t smb = smem_u32(sm);
    int t = threadIdx.x;
    int wid = t >> 5, lane = t & 31;
    int gid = lane >> 2, tig = lane & 3;
    int wm = (wid >> 1) * 64, wn = (wid & 1) * 64;
    int m0 = blockIdx.y * 128, n0 = blockIdx.x * 128, b = blockIdx.z;
    int KP = K >> 1;
    float* Yb = Y + (size_t)b * M * NSP;

    const uint32_t* base0 = Ah_g + m0;
    const uint32_t* base1 = Al_g + m0;
    const uint32_t* base2 = Bh_g + (size_t)b * KP * NSP + n0;
    const uint32_t* base3 = Bl_g + (size_t)b * KP * NSP + n0;

    int lr = t >> 5;          // 0..3 -> row part
    int lc = lane * 4;        // word col 0..124

    float c[4][8][4];
    #pragma unroll
    for (int mi = 0; mi < 4; mi++)
        #pragma unroll
        for (int nj = 0; nj < 8; nj++)
            #pragma unroll
            for (int q = 0; q < 4; q++) c[mi][nj][q] = 0.f;

    auto ld_chunk = [&](int kc, int stage) {
        uint32_t sbase = smb + 4u * (stage * STAGEW);
        #pragma unroll
        for (int i = 0; i < 16; i++) {
            const int p = i >> 2;
            int r = (i & 3) * 4 + lr;
            const uint32_t* g;
            if (p == 0)      g = base0 + (size_t)(kc * KPC + r) * M + lc;
            else if (p == 1) g = base1 + (size_t)(kc * KPC + r) * M + lc;
            else if (p == 2) g = base2 + (size_t)(kc * KPC + r) * NSP + lc;
            else             g = base3 + (size_t)(kc * KPC + r) * NSP + lc;
            cp16(sbase + 4u * (p * PLANEW + r * PSTR + lc), g);
        }
        CP_COMMIT();
    };

    int T = K / 32;
    ld_chunk(0, 0);
    ld_chunk(1, 1);

    int stage = 0;
    for (int kc = 0; kc < T; kc++) {
        CP_WAIT1();
        __syncthreads();
        if (kc + 2 < T) ld_chunk(kc + 2, (kc + 2) % 3);
        else CP_COMMIT();

        const uint32_t* S  = sm + stage * STAGEW;
        const uint32_t* Ah = S;
        const uint32_t* Al = S + PLANEW;
        const uint32_t* Bh = S + 2 * PLANEW;
        const uint32_t* Bl = S + 3 * PLANEW;

        #pragma unroll
        for (int st = 0; st < 2; st++) {
            int r0 = (st * 8 + tig) * PSTR, r1 = r0 + 4 * PSTR;
            uint32_t ah[4][4], bh[8][2];
            #pragma unroll
            for (int mi = 0; mi < 4; mi++) {
                int mo = wm + 16 * mi + gid;
                ah[mi][0] = Ah[r0 + mo]; ah[mi][1] = Ah[r0 + mo + 8];
                ah[mi][2] = Ah[r1 + mo]; ah[mi][3] = Ah[r1 + mo + 8];
            }
            #pragma unroll
            for (int nj = 0; nj < 8; nj++) {
                int no = wn + 8 * nj + gid;
                bh[nj][0] = Bh[r0 + no]; bh[nj][1] = Bh[r1 + no];
            }
            #pragma unroll
            for (int mi = 0; mi < 4; mi++)
                #pragma unroll
                for (int nj = 0; nj < 8; nj++) mma16(c[mi][nj], ah[mi], bh[nj]);
            {
                uint32_t bl[8][2];
                #pragma unroll
                for (int nj = 0; nj < 8; nj++) {
                    int no = wn + 8 * nj + gid;
                    bl[nj][0] = Bl[r0 + no]; bl[nj][1] = Bl[r1 + no];
                }
                #pragma unroll
                for (int mi = 0; mi < 4; mi++)
                    #pragma unroll
                    for (int nj = 0; nj < 8; nj++) mma16(c[mi][nj], ah[mi], bl[nj]);
            }
            {
                uint32_t al[4][4];
                #pragma unroll
                for (int mi = 0; mi < 4; mi++) {
                    int mo = wm + 16 * mi + gid;
                    al[mi][0] = Al[r0 + mo]; al[mi][1] = Al[r0 + mo + 8];
                    al[mi][2] = Al[r1 + mo]; al[mi][3] = Al[r1 + mo + 8];
                }
                #pragma unroll
                for (int mi = 0; mi < 4; mi++)
                    #pragma unroll
                    for (int nj = 0; nj < 8; nj++) mma16(c[mi][nj], al[mi], bh[nj]);
            }
        }
        stage = (stage + 1 == 3) ? 0 : stage + 1;
    }

    // epilogue: frag rows gid/gid+8, cols 2tig/2tig+1
    #pragma unroll
    for (int mi = 0; mi < 4; mi++) {
        int m = m0 + wm + 16 * mi + gid;
        float* y0 = Yb + (size_t)m * NSP + n0 + wn + 2 * tig;
        float* y1 = y0 + (size_t)8 * NSP;
        #pragma unroll
        for (int nj = 0; nj < 8; nj++) {
            *(float2*)(y0 + nj * 8) = make_float2(c[mi][nj][0], c[mi][nj][1]);
            *(float2*)(y1 + nj * 8) = make_float2(c[mi][nj][2], c[mi][nj][3]);
        }
    }

    if (STATS) {
        __syncthreads();                 // pipeline smem no longer read; reuse
        float* ssum = (float*)sm;        // [128]
        float* ssq  = (float*)sm + 128;  // [128]
        if (t < 128) { ssum[t] = 0.f; ssq[t] = 0.f; }
        __syncthreads();
        #pragma unroll
        for (int mi = 0; mi < 4; mi++) {
            float s0 = 0.f, q0 = 0.f, s1 = 0.f, q1 = 0.f;
            #pragma unroll
            for (int nj = 0; nj < 8; nj++) {
                s0 += c[mi][nj][0] + c[mi][nj][1];
                q0 += c[mi][nj][0] * c[mi][nj][0] + c[mi][nj][1] * c[mi][nj][1];
                s1 += c[mi][nj][2] + c[mi][nj][3];
                q1 += c[mi][nj][2] * c[mi][nj][2] + c[mi][nj][3] * c[mi][nj][3];
            }
            #pragma unroll
            for (int off = 1; off <= 2; off <<= 1) {
                s0 += __shfl_xor_sync(0xffffffffu, s0, off);
                q0 += __shfl_xor_sync(0xffffffffu, q0, off);
                s1 += __shfl_xor_sync(0xffffffffu, s1, off);
                q1 += __shfl_xor_sync(0xffffffffu, q1, off);
            }
            if (tig == 0) {
                int r = wm + 16 * mi + gid;
                atomicAdd(&ssum[r], s0);     atomicAdd(&ssq[r], q0);
                atomicAdd(&ssum[r + 8], s1); atomicAdd(&ssq[r + 8], q1);
            }
        }
        __syncthreads();
        if (t < 128) {
            atomicAdd(&psum[m0 + t], ssum[t]);
            atomicAdd(&psqr[m0 + t], ssq[t]);
        }
    }
}

// ---------------- attention ----------------
__global__ __launch_bounds__(256)
void attn_qk(const float* __restrict__ qkv, float* __restrict__ spart) {
    int bid = blockIdx.x, quarter = blockIdx.y;
    int b = bid >> 5, h = (bid >> 2) & 7, q = bid & 3;
    const float* base = qkv + (size_t)b * 3072 * NSP;
    const float* Qp = base + ((size_t)(h * 96 + 0)  * 4 + q) * NSP;
    const float* Kp = base + ((size_t)(h * 96 + 32) * 4 + q) * NSP;
    const size_t RS = (size_t)4 * NSP;

    __shared__ float Qs[32][132];
    __shared__ float Ks[32][132];
    __shared__ float sred[4][32][32];

    int t = threadIdx.x;
    int kg = t >> 6, lt = t & 63;
    int c0 = lt >> 3, d0 = lt & 7, kb = kg * 32;

    float s[4][4];
    #pragma unroll
    for (int i = 0; i < 4; i++)
        #pragma unroll
        for (int j = 0; j < 4; j++) s[i][j] = 0.f;

    int nbeg = quarter * 1024;
    for (int n0 = nbeg; n0 < nbeg + 1024; n0 += 128) {
        #pragma unroll
        for (int i = 0; i < 4; i++) {
            int fl = t + i * 256;
            int r = fl >> 5, cc = fl & 31;
            *(float4*)&Qs[r][cc * 4] = *(const float4*)&Qp[(size_t)r * RS + n0 + cc * 4];
            *(float4*)&Ks[r][cc * 4] = *(const float4*)&Kp[(size_t)r * RS + n0 + cc * 4];
        }
        __syncthreads();
        for (int kk = 0; kk < 32; kk++) {
            float qv[4], kv[4];
            #pragma unroll
            for (int i = 0; i < 4; i++) qv[i] = Qs[c0 + 8 * i][kb + kk];
            #pragma unroll
            for (int j = 0; j < 4; j++) kv[j] = Ks[d0 + 8 * j][kb + kk];
            #pragma unroll
            for (int i = 0; i < 4; i++)
                #pragma unroll
                for (int j = 0; j < 4; j++) s[i][j] += qv[i] * kv[j];
        }
        __syncthreads();
    }
    #pragma unroll
    for (int i = 0; i < 4; i++)
        #pragma unroll
        for (int j = 0; j < 4; j++)
            sred[kg][c0 + 8 * i][d0 + 8 * j] = s[i][j];
    __syncthreads();

    float* sp = spart + ((size_t)bid * 4 + quarter) * 1024;
    for (int e = t; e < 1024; e += 256) {
        int cc = e >> 5, dd = e & 31;
        sp[e] = sred[0][cc][dd] + sred[1][cc][dd] + sred[2][cc][dd] + sred[3][cc][dd];
    }
}

// attn_av with inline softmax + register blocking
__global__ __launch_bounds__(256)
void attn_av(const float* __restrict__ qkv, const float* __restrict__ spart,
             float* __restrict__ o) {
    int bid = blockIdx.x, quarter = blockIdx.y;
    int b = bid >> 5, h = (bid >> 2) & 7, q = bid & 3;
    const float* Vp = qkv + (size_t)b * 3072 * NSP + ((size_t)(h * 96 + 64) * 4 + q) * NSP;
    const size_t RS = (size_t)4 * NSP;

    __shared__ float Sm[32][32];
    int t = threadIdx.x;
    if (t < 32) {
        int c = t;
        const float* sp = spart + (size_t)bid * 4096;
        float rowv[32];
        float mx = -1e30f;
        #pragma unroll
        for (int d = 0; d < 32; d++) {
            float v = (sp[c * 32 + d] + sp[1024 + c * 32 + d] +
                       sp[2048 + c * 32 + d] + sp[3072 + c * 32 + d]) * SCALE_ATTN;
            rowv[d] = v; mx = fmaxf(mx, v);
        }
        float sum = 0.f;
        #pragma unroll
        for (int d = 0; d < 32; d++) { float e = expf(rowv[d] - mx); rowv[d] = e; sum += e; }
        float inv = 1.f / sum;
        #pragma unroll
        for (int d = 0; d < 32; d++) Sm[c][d] = rowv[d] * inv;
    }
    __syncthreads();

    float* ob = o + (size_t)b * CHF * NSP;
    int n = quarter * 1024 + t * 4;

    #pragma unroll
    for (int half = 0; half < 2; half++) {
        float acc[16][4];
        #pragma unroll
        for (int c = 0; c < 16; c++)
            #pragma unroll
            for (int i = 0; i < 4; i++) acc[c][i] = 0.f;
        #pragma unroll 4
        for (int d = 0; d < 32; d++) {
            float4 v4 = *(const float4*)(Vp + (size_t)d * RS + n);
            #pragma unroll
            for (int c = 0; c < 16; c++) {
                float s = Sm[half * 16 + c][d];
                acc[c][0] += s * v4.x; acc[c][1] += s * v4.y;
                acc[c][2] += s * v4.z; acc[c][3] += s * v4.w;
            }
        }
        #pragma unroll
        for (int c = 0; c < 16; c++) {
            int cc = half * 16 + c;
            *(float4*)(ob + ((size_t)((h * 32 + cc) * 4 + q)) * NSP + n) =
                make_float4(acc[c][0], acc[c][1], acc[c][2], acc[c][3]);
        }
    }
}

// ---------------- grouped 3x3 quaternion conv + residual -> bf16 planes directly ----------------
__global__ __launch_bounds__(256)
void peconv_kernel(const float* __restrict__ in, const float* __restrict__ wpe,
                   uint32_t* __restrict__ hi, uint32_t* __restrict__ lo) {
    extern __shared__ float smem[];
    float* ins = smem;
    float* wts = smem + 19008;

    int ytile = blockIdx.x, g = blockIdx.y, b = blockIdx.z;
    int t = threadIdx.x;
    int lane = t & 31, w = t >> 5;

    const float* inb = in + ((size_t)b * CHF + g * 16) * NSP;
    for (int idx = t; idx < 16 * 18 * 66; idx += 256) {
        int xx = idx % 66; int r = idx / 66;
        int yy = r % 18;   int ci = r / 18;
        int gy = ytile * 16 + yy - 1;
        int gx = xx - 1;
        float v = 0.f;
        if (gy >= 0 && gy < 64 && gx >= 0 && gx < 64)
            v = inb[(size_t)ci * NSP + gy * 64 + gx];
        ins[idx] = v;
    }
    for (int idx = t; idx < 16 * 16 * 9; idx += 256) {
        int kidx = idx % 9; int r = idx / 9;
        int ci = r % 16;    int oc = r / 16;
        wts[idx] = wpe[((size_t)(g * 16 + oc)) * (16 * 9) + ci * 9 + kidx];
    }
    __syncthreads();

    int oc = t >> 4, ly = t & 15;
    int gy = ytile * 16 + ly;
    const float* wrow = wts + oc * (16 * 9);
    size_t fbase = ((size_t)b * 512 + g * 8 + w) * NSP + (size_t)gy * 64;

    for (int x0 = 0; x0 < 64; x0 += 16) {
        float acc[16];
        #pragma unroll
        for (int xi = 0; xi < 16; xi++)
            acc[xi] = ins[(oc * 18 + ly + 1) * 66 + x0 + xi + 1];   // residual
        for (int ci = 0; ci < 16; ci++) {
            #pragma unroll
            for (int kh = 0; kh < 3; kh++) {
                const float* ir = &ins[(ci * 18 + ly + kh) * 66 + x0];
                float w0 = wrow[ci * 9 + kh * 3 + 0];
                float w1 = wrow[ci * 9 + kh * 3 + 1];
                float w2 = wrow[ci * 9 + kh * 3 + 2];
                #pragma unroll
                for (int xi = 0; xi < 16; xi++)
                    acc[xi] += w0 * ir[xi] + w1 * ir[xi + 1] + w2 * ir[xi + 2];
            }
        }
        #pragma unroll
        for (int xi = 0; xi < 16; xi++) {
            float other = __shfl_xor_sync(0xffffffffu, acc[xi], 16);
            if (lane < 16) {
                uint32_t wh, wl;
                split2(acc[xi], other, wh, wl);
                hi[fbase + x0 + xi] = wh;
                lo[fbase + x0 + xi] = wl;
            }
        }
    }
}
#define PE_SMEM ((19008 + 2304) * 4)

// ---------------- fused BN(inline coeff) + residual, emitting split planes ONLY ----------------
__global__ void ew_res_split(const float* __restrict__ X, const float* __restrict__ Yg,
                             const float* __restrict__ psum, const float* __restrict__ psqr,
                             const float* __restrict__ gamma, const float* __restrict__ beta,
                             uint32_t* __restrict__ hi, uint32_t* __restrict__ lo, int Mch) {
    size_t i4 = (size_t)blockIdx.x * 256 + threadIdx.x;
    size_t tot = (size_t)BATCH * (Mch / 2) * (NSP / 4);
    if (i4 >= tot) return;
    size_t f = i4 / (NSP / 4);
    int n = (int)(i4 % (NSP / 4)) * 4;
    int ch0 = (int)((2 * f) % Mch);
    float s0, h0, s1, h1;
    bn_coeff(psum, psqr, gamma, beta, ch0, s0, h0);
    bn_coeff(psum, psqr, gamma, beta, ch0 + 1, s1, h1);
    float4 y0 = *(const float4*)(Yg + (2 * f) * NSP + n);
    float4 y1 = *(const float4*)(Yg + (2 * f + 1) * NSP + n);
    float4 xv0 = *(const float4*)(X + (2 * f) * NSP + n);
    float4 xv1 = *(const float4*)(X + (2 * f + 1) * NSP + n);
    float4 r0, r1;
    r0.x = xv0.x + y0.x * s0 + h0; r0.y = xv0.y + y0.y * s0 + h0;
    r0.z = xv0.z + y0.z * s0 + h0; r0.w = xv0.w + y0.w * s0 + h0;
    r1.x = xv1.x + y1.x * s1 + h1; r1.y = xv1.y + y1.y * s1 + h1;
    r1.z = xv1.z + y1.z * s1 + h1; r1.w = xv1.w + y1.w * s1 + h1;
    uint32_t wh[4], wl[4];
    split2(r0.x, r1.x, wh[0], wl[0]);
    split2(r0.y, r1.y, wh[1], wl[1]);
    split2(r0.z, r1.z, wh[2], wl[2]);
    split2(r0.w, r1.w, wh[3], wl[3]);
    *(uint4*)(hi + f * NSP + n) = make_uint4(wh[0], wh[1], wh[2], wh[3]);
    *(uint4*)(lo + f * NSP + n) = make_uint4(wl[0], wl[1], wl[2], wl[3]);
}

// ---------------- fused BN(inline) + relu, emitting split planes only ----------------
__global__ void ew_relu_split(const float* __restrict__ Yg,
                              const float* __restrict__ psum, const float* __restrict__ psqr,
                              const float* __restrict__ gamma, const float* __restrict__ beta,
                              uint32_t* __restrict__ hi, uint32_t* __restrict__ lo, int Mch) {
    size_t i4 = (size_t)blockIdx.x * 256 + threadIdx.x;
    size_t tot = (size_t)BATCH * (Mch / 2) * (NSP / 4);
    if (i4 >= tot) return;
    size_t f = i4 / (NSP / 4);
    int n = (int)(i4 % (NSP / 4)) * 4;
    int ch0 = (int)((2 * f) % Mch);
    float s0, h0, s1, h1;
    bn_coeff(psum, psqr, gamma, beta, ch0, s0, h0);
    bn_coeff(psum, psqr, gamma, beta, ch0 + 1, s1, h1);
    float4 y0 = *(const float4*)(Yg + (2 * f) * NSP + n);
    float4 y1 = *(const float4*)(Yg + (2 * f + 1) * NSP + n);
    float4 r0, r1;
    r0.x = fmaxf(y0.x * s0 + h0, 0.f); r0.y = fmaxf(y0.y * s0 + h0, 0.f);
    r0.z = fmaxf(y0.z * s0 + h0, 0.f); r0.w = fmaxf(y0.w * s0 + h0, 0.f);
    r1.x = fmaxf(y1.x * s1 + h1, 0.f); r1.y = fmaxf(y1.y * s1 + h1, 0.f);
    r1.z = fmaxf(y1.z * s1 + h1, 0.f); r1.w = fmaxf(y1.w * s1 + h1, 0.f);
    uint32_t wh[4], wl[4];
    split2(r0.x, r1.x, wh[0], wl[0]);
    split2(r0.y, r1.y, wh[1], wl[1]);
    split2(r0.z, r1.z, wh[2], wl[2]);
    split2(r0.w, r1.w, wh[3], wl[3]);
    *(uint4*)(hi + f * NSP + n) = make_uint4(wh[0], wh[1], wh[2], wh[3]);
    *(uint4*)(lo + f * NSP + n) = make_uint4(wl[0], wl[1], wl[2], wl[3]);
}

// ---------------- final BN(inline) + residual; x1 reconstructed from planes ----------------
__global__ void ew_bn_res_planes(const uint32_t* __restrict__ x1h, const uint32_t* __restrict__ x1l,
                                 const float* __restrict__ Yg,
                                 const float* __restrict__ psum, const float* __restrict__ psqr,
                                 const float* __restrict__ gamma, const float* __restrict__ beta,
                                 float* __restrict__ out, int Mch) {
    size_t i4 = (size_t)blockIdx.x * 256 + threadIdx.x;
    size_t tot = (size_t)BATCH * (Mch / 2) * (NSP / 4);
    if (i4 >= tot) return;
    size_t f = i4 / (NSP / 4);
    int n = (int)(i4 % (NSP / 4)) * 4;
    int ch0 = (int)((2 * f) % Mch);
    float s0, h0, s1, h1;
    bn_coeff(psum, psqr, gamma, beta, ch0, s0, h0);
    bn_coeff(psum, psqr, gamma, beta, ch0 + 1, s1, h1);
    uint4 vh = *(const uint4*)(x1h + f * NSP + n);
    uint4 vl = *(const uint4*)(x1l + f * NSP + n);
    float4 y0 = *(const float4*)(Yg + (2 * f) * NSP + n);
    float4 y1 = *(const float4*)(Yg + (2 * f + 1) * NSP + n);
    float4 x0, x1v;
    recon2(vh.x, vl.x, x0.x, x1v.x);
    recon2(vh.y, vl.y, x0.y, x1v.y);
    recon2(vh.z, vl.z, x0.z, x1v.z);
    recon2(vh.w, vl.w, x0.w, x1v.w);
    float4 r0, r1;
    r0.x = x0.x + y0.x * s0 + h0; r0.y = x0.y + y0.y * s0 + h0;
    r0.z = x0.z + y0.z * s0 + h0; r0.w = x0.w + y0.w * s0 + h0;
    r1.x = x1v.x + y1.x * s1 + h1; r1.y = x1v.y + y1.y * s1 + h1;
    r1.z = x1v.z + y1.z * s1 + h1; r1.w = x1v.w + y1.w * s1 + h1;
    *(float4*)(out + (2 * f) * NSP + n) = r0;
    *(float4*)(out + (2 * f + 1) * NSP + n) = r1;
}

// ---------------- host launcher ----------------
extern "C" void kernel_launch(void* const* d_in, const int* in_sizes, int n_in,
                              void* d_out, int out_size) {
    const float* x      = (const float*)d_in[0];
    const float* w_qkv  = (const float*)d_in[1];
    const float* w_proj = (const float*)d_in[2];
    const float* w_pe   = (const float*)d_in[3];
    const float* gn     = (const float*)d_in[4];
    const float* bn     = (const float*)d_in[5];
    const float* w_f1   = (const float*)d_in[6];
    const float* gf1    = (const float*)d_in[7];
    const float* bf1    = (const float*)d_in[8];
    const float* w_f2   = (const float*)d_in[9];
    const float* gf2    = (const float*)d_in[10];
    const float* bf2    = (const float*)d_in[11];
    float* out = (float*)d_out;

    void *p;
    uint32_t *qh, *ql, *ph, *pl, *f1h, *f1l, *f2h, *f2l;
    uint32_t *xh, *xl, *o2h, *o2l, *x1h, *x1l, *fbh, *fbl;
    float *wpe, *qkv, *attno, *tmp, *spart, *pstat;
    cudaGetSymbolAddress(&p, g_wqkv_h);  qh  = (uint32_t*)p;
    cudaGetSymbolAddress(&p, g_wqkv_l);  ql  = (uint32_t*)p;
    cudaGetSymbolAddress(&p, g_wproj_h); ph  = (uint32_t*)p;
    cudaGetSymbolAddress(&p, g_wproj_l); pl  = (uint32_t*)p;
    cudaGetSymbolAddress(&p, g_wf1_h);   f1h = (uint32_t*)p;
    cudaGetSymbolAddress(&p, g_wf1_l);   f1l = (uint32_t*)p;
    cudaGetSymbolAddress(&p, g_wf2_h);   f2h = (uint32_t*)p;
    cudaGetSymbolAddress(&p, g_wf2_l);   f2l = (uint32_t*)p;
    cudaGetSymbolAddress(&p, g_xh);      xh  = (uint32_t*)p;
    cudaGetSymbolAddress(&p, g_xl);      xl  = (uint32_t*)p;
    cudaGetSymbolAddress(&p, g_o2h);     o2h = (uint32_t*)p;
    cudaGetSymbolAddress(&p, g_o2l);     o2l = (uint32_t*)p;
    cudaGetSymbolAddress(&p, g_x1h);     x1h = (uint32_t*)p;
    cudaGetSymbolAddress(&p, g_x1l);     x1l = (uint32_t*)p;
    cudaGetSymbolAddress(&p, g_fbh);     fbh = (uint32_t*)p;
    cudaGetSymbolAddress(&p, g_fbl);     fbl = (uint32_t*)p;
    cudaGetSymbolAddress(&p, g_wpe);     wpe = (float*)p;
    cudaGetSymbolAddress(&p, g_qkv);     qkv = (float*)p;
    cudaGetSymbolAddress(&p, g_attno);   attno = (float*)p;
    cudaGetSymbolAddress(&p, g_tmp);     tmp = (float*)p;
    cudaGetSymbolAddress(&p, g_spart);   spart = (float*)p;
    cudaGetSymbolAddress(&p, g_pstat);   pstat = (float*)p;

    float* ps0 = pstat;           float* pq0 = pstat + 2048;
    float* ps1 = pstat + 4096;    float* pq1 = pstat + 6144;
    float* ps2 = pstat + 8192;    float* pq2 = pstat + 10240;

    cudaFuncSetAttribute(mma_gemm2<false>, cudaFuncAttributeMaxDynamicSharedMemorySize, GEMM_SMEM_BYTES);
    cudaFuncSetAttribute(mma_gemm2<true>,  cudaFuncAttributeMaxDynamicSharedMemorySize, GEMM_SMEM_BYTES);
    cudaFuncSetAttribute(peconv_kernel, cudaFuncAttributeMaxDynamicSharedMemorySize, PE_SMEM);

    // 0. zero stat accumulators
    cudaMemsetAsync(pstat, 0, 3 * 2 * 2048 * sizeof(float));

    // 1. weight expansions -> packed bf16 hi/lo planes
    expand_w_pk<<<(512 * 3072 + 255) / 256, 256>>>(w_qkv,  qh,  ql,  768, 256);
    expand_w_pk<<<(512 * 1024 + 255) / 256, 256>>>(w_proj, ph,  pl,  256, 256);
    expand_w_pk<<<(512 * 2048 + 255) / 256, 256>>>(w_f1,   f1h, f1l, 512, 256);
    expand_w_pk<<<(1024 * 1024 + 255) / 256, 256>>>(w_f2,  f2h, f2l, 256, 512);
    expand_pe_kernel<<<(1024 * 16 * 9 + 255) / 256, 256>>>(w_pe, wpe);

    // 2. split x -> planes, qkv GEMM (no stats)
    split_pack<<<(int)((size_t)BATCH * 512 * (NSP / 4) / 256), 256>>>(x, xh, xl, BATCH * 512);
    mma_gemm2<false><<<dim3(32, 24, BATCH), 128, GEMM_SMEM_BYTES>>>(
        qh, ql, xh, xl, qkv, nullptr, nullptr, 3072, 1024);

    // 3. channel attention
    attn_qk<<<dim3(128, 4), 256>>>(qkv, spart);
    attn_av<<<dim3(128, 4), 256>>>(qkv, spart, attno);

    // 4. positional conv + residual -> o2 planes directly
    peconv_kernel<<<dim3(4, 64, BATCH), 256, PE_SMEM>>>(attno, wpe, o2h, o2l);

    // 5. proj GEMM (+stats) + BN residual -> x1 planes only (no fp32 x1)
    mma_gemm2<true><<<dim3(32, 8, BATCH), 128, GEMM_SMEM_BYTES>>>(
        ph, pl, o2h, o2l, tmp, ps0, pq0, 1024, 1024);
    ew_res_split<<<(int)((size_t)BATCH * 512 * (NSP / 4) / 256), 256>>>(
        x, tmp, ps0, pq0, gn, bn, x1h, x1l, 1024);

    // 6. f1 GEMM (+stats) + BN relu -> fb planes
    mma_gemm2<true><<<dim3(32, 16, BATCH), 128, GEMM_SMEM_BYTES>>>(
        f1h, f1l, x1h, x1l, tmp, ps1, pq1, 2048, 1024);
    ew_relu_split<<<(int)((size_t)BATCH * 1024 * (NSP / 4) / 256), 256>>>(
        tmp, ps1, pq1, gf1, bf1, fbh, fbl, 2048);

    // 7. f2 GEMM (+stats) + BN residual -> out (x1 reconstructed from planes)
    mma_gemm2<true><<<dim3(32, 8, BATCH), 128, GEMM_SMEM_BYTES>>>(
        f2h, f2l, fbh, fbl, tmp, ps2, pq2, 1024, 2048);
    ew_bn_res_planes<<<(int)((size_t)BATCH * 512 * (NSP / 4) / 256), 256>>>(
        x1h, x1l, tmp, ps2, pq2, gf2, bf2, out, 1024);

    (void)in_sizes; (void)n_in; (void)out_size;
}